// round 13
// baseline (speedup 1.0000x reference)
#include <cuda_runtime.h>
#include <math.h>
#include <stdint.h>

#define VV   200000
#define BQ   2048
#define FF   5
#define NNB  64
#define KSEL 32
#define DD   256
#define DMV  512     // DM
#define HID  1024    // 2*DM
#define NG   2048    // packed gate cols, INTERLEAVED: col = j*4 + gate
#define MROWS (2*(BQ+FF))   // 4106 gcn rows
#define ER    (BQ + FF)     // 2053 encoder rows

// ---------------- static scratch ----------------
__device__ float g_meancat[(size_t)4224*2*DD];
__device__ float g_nb[(size_t)4224*DD];
__device__ float g_H[(size_t)2176*2*DMV];
__device__ float g_O[(size_t)2176*DMV];
__device__ float g_enc[(size_t)2176*DMV];
__device__ float g_sg[DMV];
__device__ float g_sgn[DMV];
__device__ float g_sgr[NG];
__device__ float g_biasp[NG];
__device__ float g_Gbase[(size_t)BQ*NG];
__device__ float g_c[BQ*DMV];
__device__ float g_h1[BQ*DMV];
__device__ float g_h2[BQ*DMV];

// packed bf16x2 weights (fragment order, k16 blocks): [pBlock128][kBlock16][1024]
__device__ unsigned g_wih_h[(size_t)16*32*1024],  g_wih_l[(size_t)16*32*1024];
__device__ unsigned g_whh_h[(size_t)16*32*1024],  g_whh_l[(size_t)16*32*1024];
__device__ unsigned g_p1w_h[(size_t)8*32*1024],   g_p1w_l[(size_t)8*32*1024];
__device__ unsigned g_p2w_h[(size_t)4*64*1024],   g_p2w_l[(size_t)4*64*1024];
__device__ unsigned g_gcnw_h[(size_t)2*32*1024],  g_gcnw_l[(size_t)2*32*1024];

// ---------------- helpers ----------------
__device__ __forceinline__ float warp_reduce_sum(float v) {
#pragma unroll
    for (int o = 16; o > 0; o >>= 1) v += __shfl_down_sync(0xffffffffu, v, o);
    return v;
}
__device__ __forceinline__ float sigmoidf_(float x) { return 1.0f / (1.0f + expf(-x)); }
__device__ __forceinline__ int clamp_id(int id) { return (id < 0 || id > VV) ? VV : id; }

__device__ __forceinline__ float block_reduce_256(float v, float* red) {
    int lane = threadIdx.x & 31, w = threadIdx.x >> 5;
    v = warp_reduce_sum(v);
    if (lane == 0) red[w] = v;
    __syncthreads();
    if (threadIdx.x == 0) {
        float s = 0.f;
#pragma unroll
        for (int i = 0; i < 8; i++) s += red[i];
        red[0] = s;
    }
    __syncthreads();
    float s = red[0];
    __syncthreads();
    return s;
}

__device__ __forceinline__ unsigned short f2bf(float x) {
    unsigned short r;
    asm("cvt.rn.bf16.f32 %0, %1;" : "=h"(r) : "f"(x));
    return r;
}
__device__ __forceinline__ float bf2f(unsigned short b) {
    return __uint_as_float((unsigned)b << 16);
}

__device__ __forceinline__ void mma_bf16(float* c, const unsigned* a, const unsigned* b) {
    asm volatile(
        "mma.sync.aligned.m16n8k16.row.col.f32.bf16.bf16.f32 "
        "{%0,%1,%2,%3}, {%4,%5,%6,%7}, {%8,%9}, {%0,%1,%2,%3};"
        : "+f"(c[0]), "+f"(c[1]), "+f"(c[2]), "+f"(c[3])
        : "r"(a[0]), "r"(a[1]), "r"(a[2]), "r"(a[3]), "r"(b[0]), "r"(b[1]));
}

__device__ __forceinline__ void cp16(unsigned* smem, const unsigned* g) {
    unsigned sa = (unsigned)__cvta_generic_to_shared(smem);
    asm volatile("cp.async.cg.shared.global [%0], [%1], 16;" :: "r"(sa), "l"(g));
}
__device__ __forceinline__ void cp_commit() { asm volatile("cp.async.commit_group;"); }
__device__ __forceinline__ void cp_wait0()  { asm volatile("cp.async.wait_group 0;"); }

// ---------------- weight pack: bf16x2 k16 fragment order ----------------
// gateHid==0: orig row = p*128 + col (plain).
// gateHid!=0: INTERLEAVED gate cols: global col gc = p*128+col -> orig row = (gc&3)*gateHid + (gc>>2)
__global__ __launch_bounds__(256) void packw16_kernel(
    const float* __restrict__ W, int ld, int gateHid,
    unsigned* __restrict__ ph, unsigned* __restrict__ pl)
{
    int kb = blockIdx.x, p = blockIdx.y, kBlocks = gridDim.x;
    unsigned* oh = ph + ((size_t)p * kBlocks + kb) * 1024;
    unsigned* ol = pl + ((size_t)p * kBlocks + kb) * 1024;
#pragma unroll
    for (int w = threadIdx.x; w < 1024; w += 256) {
        int nblk = w >> 6, rem = w & 63;
        int lane = rem >> 1, reg = rem & 1;
        int col = nblk * 8 + (lane >> 2);
        int k0 = reg * 8 + (lane & 3) * 2;
        int gc = p * 128 + col;
        int orow = gateHid ? ((gc & 3) * gateHid + (gc >> 2)) : gc;
        const float* wr = W + (size_t)orow * ld + kb * 16 + k0;
        float v0 = wr[0], v1 = wr[1];
        unsigned short h0 = f2bf(v0), h1 = f2bf(v1);
        unsigned short l0 = f2bf(v0 - bf2f(h0)), l1 = f2bf(v1 - bf2f(h1));
        oh[w] = (unsigned)h0 | ((unsigned)h1 << 16);
        ol[w] = (unsigned)l0 | ((unsigned)l1 << 16);
    }
}

// ---------------- neighbor encoder: top-K select + mean of (rel,ent) ----------------
// dynamic smem: entz[64][256] fp32 cache of ent rows (filled during sim pass)
__global__ __launch_bounds__(256) void nbenc_kernel(
    const int* __restrict__ query, const int* __restrict__ support,
    const int* __restrict__ qlc, const int* __restrict__ qrc,
    const int* __restrict__ slc, const int* __restrict__ srrc,
    const float* __restrict__ emb, float* __restrict__ meancat_out)
{
    extern __shared__ float entz[];   // 64 * 256 floats = 64 KB
    int row = blockIdx.x, side = blockIdx.y;
    const int* conn; int id; int r;
    if (row < BQ) {
        conn = (side == 0 ? qlc : qrc) + row * NNB * 2;
        id   = query[row * 2 + side];
        r    = row * 2 + side;
    } else {
        int f = row - BQ;
        conn = (side == 0 ? slc : srrc) + f * NNB * 2;
        id   = support[f * 2 + side];
        r    = 2 * BQ + f * 2 + side;
    }
    id = clamp_id(id);
    int t = threadIdx.x, lane = t & 31, warp = t >> 5;

    __shared__ __align__(16) float csm[DD];
    __shared__ float sims[NNB];
    __shared__ int   sel[NNB];
    __shared__ float red[8];
    __shared__ float cn_s;

    float cv = emb[(size_t)id * DD + t];
    csm[t] = cv;
    float cs = block_reduce_256(cv * cv, red);
    if (t == 0) cn_s = sqrtf(cs);
    __syncthreads();

    float4 c0 = *(const float4*)&csm[lane * 8];
    float4 c1 = *(const float4*)&csm[lane * 8 + 4];

#pragma unroll
    for (int i = 0; i < 8; i++) {
        int n = warp * 8 + i;
        int eid = clamp_id(conn[n * 2 + 1]);
        const float4* er4 = (const float4*)(emb + (size_t)eid * DD);
        float4 e0 = er4[lane * 2];
        float4 e1 = er4[lane * 2 + 1];
        *(float4*)&entz[n * DD + lane * 8]     = e0;
        *(float4*)&entz[n * DD + lane * 8 + 4] = e1;
        float dot = e0.x*c0.x + e0.y*c0.y + e0.z*c0.z + e0.w*c0.w
                  + e1.x*c1.x + e1.y*c1.y + e1.z*c1.z + e1.w*c1.w;
        float nn2 = e0.x*e0.x + e0.y*e0.y + e0.z*e0.z + e0.w*e0.w
                  + e1.x*e1.x + e1.y*e1.y + e1.z*e1.z + e1.w*e1.w;
        dot = warp_reduce_sum(dot);
        nn2 = warp_reduce_sum(nn2);
        if (lane == 0) sims[n] = dot / fmaxf(cn_s * sqrtf(nn2), 1e-8f);
    }
    __syncthreads();

    if (t < NNB) {
        float s = sims[t];
        int cnt = 0;
#pragma unroll
        for (int m = 0; m < NNB; m++) {
            float sm = sims[m];
            cnt += (sm > s) || (sm == s && m < t);
        }
        sel[t] = (cnt < KSEL);
    }
    __syncthreads();

    float accR = 0.f, accE = 0.f;
    for (int n = 0; n < NNB; n++) {
        if (!sel[n]) continue;
        int rid = clamp_id(conn[n * 2 + 0]);
        accR += emb[(size_t)rid * DD + t];
        accE += entz[n * DD + t];
    }
    float* mc = meancat_out + (size_t)r * (2 * DD);
    mc[t]      = accR * (1.0f / KSEL);
    mc[DD + t] = accE * (1.0f / KSEL);
}

// ---------------- unified 3xBF16 GEMM: m16n8k16, 2 smem stages, cp.async B ----------------
// C[M x 128*gx] = epi(A[M x 16*kBlocks] @ Wpacked^T + ...). CTA tile (MI*32) x 128.
// EPI: 0 = acc + v1 + addmat; 1 = tanh(acc+v1+v2); 2 = relu(acc+v1)
// LSTM: 0 = plain; 1 = Gbase+step1 (c=0; write C and c/h); 2 = step (addmat=Gbase; write c/h only)
template<int EPI, int MI, int LSTM>
__global__ __launch_bounds__(256, 2) void tgemm_bf(
    const float* __restrict__ A, int lda, int Mtot,
    const unsigned* __restrict__ Wh, const unsigned* __restrict__ Wl, int kBlocks,
    float* __restrict__ C, int ldc,
    const float* __restrict__ addmat, int ldm,
    const float* __restrict__ v1, const float* __restrict__ v2,
    const float* __restrict__ qg, float* __restrict__ cc, float* __restrict__ hh)
{
    constexpr int BM = MI * 32;                 // 64 or 128
    __shared__ unsigned Ash[2][BM * 8], Asl[2][BM * 8];
    __shared__ unsigned Bsh[2][1024], Bsl[2][1024];

    const int t = threadIdx.x;
    const int lane = t & 31, warp = t >> 5;
    const int wy = warp >> 2, wx = warp & 3;
    const int m0 = blockIdx.y * BM, n0 = blockIdx.x * 128;

    const unsigned* WH = Wh + (size_t)(n0 >> 7) * kBlocks * 1024;
    const unsigned* WL = Wl + (size_t)(n0 >> 7) * kBlocks * 1024;

    const bool astage = (t < BM * 2);
    const int row = t >> 1;
    const int kin = (t & 1) * 8;
    int ar = m0 + row; if (ar >= Mtot) ar = Mtot - 1;
    const float* Ap = A + (size_t)ar * lda + kin;
    const int baseA = (row >> 4) * 128 + (row & 7) * 16 + (((row & 15) >= 8) ? 1 : 0) + (kin ? 2 : 0);

    float acc[MI][4][4];
#pragma unroll
    for (int i = 0; i < MI; i++)
#pragma unroll
        for (int n = 0; n < 4; n++)
#pragma unroll
            for (int q = 0; q < 4; q++) acc[i][n][q] = 0.f;

    cp16(&Bsh[0][t * 4], WH + t * 4);
    cp16(&Bsl[0][t * 4], WL + t * 4);
    cp_commit();
    float4 va0, va1;
    if (astage) {
        va0 = *(const float4*)Ap;
        va1 = *(const float4*)(Ap + 4);
        float av[8] = {va0.x, va0.y, va0.z, va0.w, va1.x, va1.y, va1.z, va1.w};
#pragma unroll
        for (int j = 0; j < 4; j++) {
            unsigned short h0 = f2bf(av[2*j]),   h1 = f2bf(av[2*j+1]);
            unsigned short l0 = f2bf(av[2*j] - bf2f(h0));
            unsigned short l1 = f2bf(av[2*j+1] - bf2f(h1));
            Ash[0][baseA + j * 4] = (unsigned)h0 | ((unsigned)h1 << 16);
            Asl[0][baseA + j * 4] = (unsigned)l0 | ((unsigned)l1 << 16);
        }
    }
    cp_wait0();
    __syncthreads();

    int s = 0;
    for (int kb = 0; kb < kBlocks; kb++) {
        const bool more = (kb + 1 < kBlocks);
        if (more) {
            const unsigned* bh = WH + (size_t)(kb + 1) * 1024;
            const unsigned* bl = WL + (size_t)(kb + 1) * 1024;
            cp16(&Bsh[s ^ 1][t * 4], bh + t * 4);
            cp16(&Bsl[s ^ 1][t * 4], bl + t * 4);
            cp_commit();
            if (astage) {
                va0 = *(const float4*)(Ap + (kb + 1) * 16);
                va1 = *(const float4*)(Ap + (kb + 1) * 16 + 4);
            }
        }
        uint4 AH[MI], AL[MI];
        uint2 BH[4], BL[4];
#pragma unroll
        for (int i = 0; i < MI; i++) {
            int fi = (wy * MI + i) * 128 + lane * 4;
            AH[i] = *(const uint4*)&Ash[s][fi];
            AL[i] = *(const uint4*)&Asl[s][fi];
        }
#pragma unroll
        for (int n = 0; n < 4; n++) {
            int fn = (wx * 4 + n) * 64 + lane * 2;
            BH[n] = *(const uint2*)&Bsh[s][fn];
            BL[n] = *(const uint2*)&Bsl[s][fn];
        }
#pragma unroll
        for (int i = 0; i < MI; i++)
#pragma unroll
            for (int n = 0; n < 4; n++) {
                mma_bf16(acc[i][n], (const unsigned*)&AH[i], (const unsigned*)&BH[n]);
                mma_bf16(acc[i][n], (const unsigned*)&AL[i], (const unsigned*)&BH[n]);
                mma_bf16(acc[i][n], (const unsigned*)&AH[i], (const unsigned*)&BL[n]);
            }
        if (more) {
            if (astage) {
                float av[8] = {va0.x, va0.y, va0.z, va0.w, va1.x, va1.y, va1.z, va1.w};
#pragma unroll
                for (int j = 0; j < 4; j++) {
                    unsigned short h0 = f2bf(av[2*j]),   h1 = f2bf(av[2*j+1]);
                    unsigned short l0 = f2bf(av[2*j] - bf2f(h0));
                    unsigned short l1 = f2bf(av[2*j+1] - bf2f(h1));
                    Ash[s ^ 1][baseA + j * 4] = (unsigned)h0 | ((unsigned)h1 << 16);
                    Asl[s ^ 1][baseA + j * 4] = (unsigned)l0 | ((unsigned)l1 << 16);
                }
            }
            cp_wait0();
            __syncthreads();
            s ^= 1;
        }
    }

    // ---- epilogue ----
#pragma unroll
    for (int i = 0; i < MI; i++) {
#pragma unroll
        for (int n = 0; n < 4; n++) {
            int col = n0 + wx * 32 + n * 8 + (lane & 3) * 2;
            float v0 = 0.f, v1c = 0.f;
            if (v1) { v0 += v1[col]; v1c += v1[col + 1]; }
            if (EPI == 1 && v2) { v0 += v2[col]; v1c += v2[col + 1]; }
#pragma unroll
            for (int half = 0; half < 2; half++) {
                int m = m0 + wy * MI * 16 + i * 16 + (lane >> 2) + half * 8;
                float x0 = acc[i][n][half * 2 + 0] + v0;
                float x1 = acc[i][n][half * 2 + 1] + v1c;
                if (LSTM == 0) {
                    if (m >= Mtot) continue;
                    float* crow = C + (size_t)m * ldc + col;
                    if (EPI == 1) {
                        crow[0] = tanhf(x0); crow[1] = tanhf(x1);
                    } else if (EPI == 2) {
                        crow[0] = fmaxf(x0, 0.f); crow[1] = fmaxf(x1, 0.f);
                    } else {
                        if (addmat) {
                            const float* mr = addmat + (size_t)m * ldm + col;
                            x0 += mr[0]; x1 += mr[1];
                        }
                        crow[0] = x0; crow[1] = x1;
                    }
                } else {
                    // interleaved gates: col = j*4+g. Quad lanes r=0..3:
                    // r even holds (i,f) of j; r odd holds (g,o) of same j.
                    if (LSTM == 2) {
                        const float* mr = addmat + (size_t)m * ldm + col;
                        x0 += mr[0]; x1 += mr[1];
                    } else {
                        float* crow = C + (size_t)m * ldc + col;   // Gbase
                        crow[0] = x0; crow[1] = x1;
                    }
                    float y0 = __shfl_xor_sync(0xffffffffu, x0, 1);
                    float y1 = __shfl_xor_sync(0xffffffffu, x1, 1);
                    if ((lane & 1) == 0) {
                        int j = col >> 2;
                        int idx = m * DMV + j;
                        float cn = sigmoidf_(x0) * tanhf(y0);      // sig(i)*tanh(g)
                        if (LSTM == 2) cn += sigmoidf_(x1) * cc[idx];  // + sig(f)*c
                        cc[idx] = cn;
                        hh[idx] = qg[idx] + sigmoidf_(y1) * tanhf(cn); // qg + sig(o)*tanh(c)
                    }
                }
            }
        }
    }
}

// ---------------- LayerNorm over 512 per row ----------------
__global__ __launch_bounds__(256) void ln_kernel(
    const float* __restrict__ O, float* __restrict__ Y,
    const float* __restrict__ lng, const float* __restrict__ lnb)
{
    int row = blockIdx.x, t = threadIdx.x;
    __shared__ float red[8];
    float o0 = O[(size_t)row * DMV + t];
    float o1 = O[(size_t)row * DMV + t + 256];
    float msum = block_reduce_256(o0 + o1, red);
    float m = msum * (1.0f / DMV);
    float d0 = o0 - m, d1 = o1 - m;
    float vsum = block_reduce_256(d0 * d0 + d1 * d1, red);
    float rstd = rsqrtf(vsum * (1.0f / DMV) + 1e-5f);
    Y[(size_t)row * DMV + t]       = d0 * rstd * lng[t]       + lnb[t];
    Y[(size_t)row * DMV + t + 256] = d1 * rstd * lng[t + 256] + lnb[t + 256];
}

// ---------------- mean over F support rows + normalized copy ----------------
__global__ void avgnorm_kernel(float* __restrict__ sg, float* __restrict__ sgn,
                               const float* __restrict__ senc)
{
    int t = threadIdx.x; // 512 threads
    __shared__ float red[16];
    float s = 0.f;
#pragma unroll
    for (int f = 0; f < FF; f++) s += senc[f * DMV + t];
    s *= (1.0f / FF);
    sg[t] = s;
    int lane = t & 31, w = t >> 5;
    float v = warp_reduce_sum(s * s);
    if (lane == 0) red[w] = v;
    __syncthreads();
    if (t == 0) {
        float tot = 0.f;
#pragma unroll
        for (int i = 0; i < 16; i++) tot += red[i];
        red[0] = sqrtf(tot);
    }
    __syncthreads();
    float nrm = red[0];
    sgn[t] = s / fmaxf(nrm, 1e-12f);
}

// ---------------- packed constants: sgr[n], biasp[n] (interleaved: n = j*4+g) ----------------
__global__ __launch_bounds__(256) void pack_kernel(
    float* __restrict__ sgr, float* __restrict__ biasp,
    const float* __restrict__ whh, const float* __restrict__ sg,
    const float* __restrict__ bih, const float* __restrict__ bhh)
{
    int n = (blockIdx.x * blockDim.x + threadIdx.x) >> 5;
    int lane = threadIdx.x & 31;
    if (n >= NG) return;
    int jf = (n & 3) * HID + (n >> 2);
    const float* wr = whh + (size_t)jf * HID + DMV;
    float a = 0.f;
#pragma unroll
    for (int k = lane; k < DMV; k += 32) a += wr[k] * sg[k];
    a = warp_reduce_sum(a);
    if (lane == 0) {
        sgr[n] = a;
        biasp[n] = bih[jf] + bhh[jf];
    }
}

// ---------------- final cosine output ----------------
__global__ __launch_bounds__(256) void final_kernel(
    float* __restrict__ out, const float* __restrict__ h,
    const float* __restrict__ sgn)
{
    int b = (blockIdx.x * blockDim.x + threadIdx.x) >> 5;
    int lane = threadIdx.x & 31;
    if (b >= BQ) return;
    float nn = 0.f, dd = 0.f;
#pragma unroll
    for (int d = lane; d < DMV; d += 32) {
        float hv = h[(size_t)b * DMV + d];
        nn += hv * hv;
        dd += hv * sgn[d];
    }
    nn = warp_reduce_sum(nn);
    dd = warp_reduce_sum(dd);
    if (lane == 0) out[b] = dd / fmaxf(sqrtf(nn), 1e-12f);
}

// ---------------- input binding ----------------
enum {
    R_query=0, R_support, R_qlc, R_qld, R_qrc, R_qrd, R_slc, R_sld, R_src, R_srd,
    R_emb, R_gcnw, R_gcnwb, R_gcnb, R_p1w, R_p1b, R_p2w, R_p2b, R_lng, R_lnb,
    R_wih, R_whh, R_bih, R_bhh, R_COUNT
};
static const int DICT_SIZES[R_COUNT] = {
    4096, 10, 262144, 2048, 262144, 2048, 640, 5, 640, 5,
    51200256, 131072, 256, 256, 524288, 1024, 524288, 512, 512, 512,
    2097152, 4194304, 4096, 4096
};
static bool sizes_match(const int* s, const int* exp, int n) {
    for (int i = 0; i < n; i++) if (s[i] != exp[i]) return false;
    return true;
}

// ---------------- launcher ----------------
extern "C" void kernel_launch(void* const* d_in, const int* in_sizes, int n_in,
                              void* d_out, int out_size)
{
    int map[R_COUNT];
    if (n_in >= R_COUNT && sizes_match(in_sizes, DICT_SIZES, R_COUNT)) {
        for (int r = 0; r < R_COUNT; r++) map[r] = r;
    } else {
        bool used[64] = {false};
        for (int r = 0; r < R_COUNT; r++) {
            map[r] = 0;
            for (int i = 0; i < n_in && i < 64; i++) {
                if (!used[i] && in_sizes[i] == DICT_SIZES[r]) { map[r] = i; used[i] = true; break; }
            }
        }
    }

    const int*   query   = (const int*)d_in[map[R_query]];
    const int*   support = (const int*)d_in[map[R_support]];
    const int*   qlc     = (const int*)d_in[map[R_qlc]];
    const int*   qrc     = (const int*)d_in[map[R_qrc]];
    const int*   slc     = (const int*)d_in[map[R_slc]];
    const int*   srrc    = (const int*)d_in[map[R_src]];
    const float* emb     = (const float*)d_in[map[R_emb]];
    const float* gcnw    = (const float*)d_in[map[R_gcnw]];
    const float* gcnwb   = (const float*)d_in[map[R_gcnwb]];
    const float* gcnb    = (const float*)d_in[map[R_gcnb]];
    const float* p1w     = (const float*)d_in[map[R_p1w]];
    const float* p1b     = (const float*)d_in[map[R_p1b]];
    const float* p2w     = (const float*)d_in[map[R_p2w]];
    const float* p2b     = (const float*)d_in[map[R_p2b]];
    const float* lng     = (const float*)d_in[map[R_lng]];
    const float* lnb     = (const float*)d_in[map[R_lnb]];
    const float* wih     = (const float*)d_in[map[R_wih]];
    const float* whh     = (const float*)d_in[map[R_whh]];
    const float* bih     = (const float*)d_in[map[R_bih]];
    const float* bhh     = (const float*)d_in[map[R_bhh]];
    float* out = (float*)d_out;

    float *mc, *nb, *H, *O, *enc, *sg, *sgn, *sgr, *biasp, *Gbase, *c, *h1, *h2;
    cudaGetSymbolAddress((void**)&mc,    g_meancat);
    cudaGetSymbolAddress((void**)&nb,    g_nb);
    cudaGetSymbolAddress((void**)&H,     g_H);
    cudaGetSymbolAddress((void**)&O,     g_O);
    cudaGetSymbolAddress((void**)&enc,   g_enc);
    cudaGetSymbolAddress((void**)&sg,    g_sg);
    cudaGetSymbolAddress((void**)&sgn,   g_sgn);
    cudaGetSymbolAddress((void**)&sgr,   g_sgr);
    cudaGetSymbolAddress((void**)&biasp, g_biasp);
    cudaGetSymbolAddress((void**)&Gbase, g_Gbase);
    cudaGetSymbolAddress((void**)&c,     g_c);
    cudaGetSymbolAddress((void**)&h1,    g_h1);
    cudaGetSymbolAddress((void**)&h2,    g_h2);

    unsigned *wihh, *wihl, *whhh, *whhl, *p1h, *p1l, *p2h, *p2l, *gch, *gcl;
    cudaGetSymbolAddress((void**)&wihh, g_wih_h);  cudaGetSymbolAddress((void**)&wihl, g_wih_l);
    cudaGetSymbolAddress((void**)&whhh, g_whh_h);  cudaGetSymbolAddress((void**)&whhl, g_whh_l);
    cudaGetSymbolAddress((void**)&p1h,  g_p1w_h);  cudaGetSymbolAddress((void**)&p1l,  g_p1w_l);
    cudaGetSymbolAddress((void**)&p2h,  g_p2w_h);  cudaGetSymbolAddress((void**)&p2l,  g_p2w_l);
    cudaGetSymbolAddress((void**)&gch,  g_gcnw_h); cudaGetSymbolAddress((void**)&gcl,  g_gcnw_l);

    float* qg   = enc;
    float* senc = enc + (size_t)BQ * DMV;

    // nbenc needs 64 KB dynamic smem
    cudaFuncSetAttribute(nbenc_kernel, cudaFuncAttributeMaxDynamicSharedMemorySize, 65536);

    // 0) pack weights (bf16x2 hi/lo, k16 fragment order; gates interleaved)
    packw16_kernel<<<dim3(32, 2),  256>>>(gcnw, 512,  0,    gch,  gcl);
    packw16_kernel<<<dim3(32, 8),  256>>>(p1w,  512,  0,    p1h,  p1l);
    packw16_kernel<<<dim3(64, 4),  256>>>(p2w,  1024, 0,    p2h,  p2l);
    packw16_kernel<<<dim3(32, 16), 256>>>(wih,  512,  HID,  wihh, wihl);
    packw16_kernel<<<dim3(32, 16), 256>>>(whh,  1024, HID,  whhh, whhl);

    // 1) neighbor top-K means -> meancat (4106 x 512)
    nbenc_kernel<<<dim3(BQ + FF, 2), 256, 65536>>>(query, support, qlc, qrc, slc, srrc, emb, mc);
    // 2) GCN: nb = tanh(mc @ gcnw^T + wb + b)
    tgemm_bf<1,2,0><<<dim3(2, 65), 256>>>(mc, 2*DD, MROWS, gch, gcl, 32,
                                          nb, DD, nullptr, 0, gcnwb, gcnb,
                                          nullptr, nullptr, nullptr);
    // 3) encoder batched over 2053 rows
    tgemm_bf<2,2,0><<<dim3(8, 33), 256>>>(nb, DMV, ER, p1h, p1l, 32,
                                          H, 2*DMV, nullptr, 0, p1b, nullptr,
                                          nullptr, nullptr, nullptr);
    tgemm_bf<0,2,0><<<dim3(4, 33), 256>>>(H, 2*DMV, ER, p2h, p2l, 64,
                                          O, DMV, nb, DMV, p2b, nullptr,
                                          nullptr, nullptr, nullptr);
    ln_kernel<<<ER, 256>>>(O, enc, lng, lnb);
    // 4) support_g mean + normalized copy
    avgnorm_kernel<<<1, 512>>>(sg, sgn, senc);
    // 5) packed sgr + bias (interleaved)
    pack_kernel<<<NG / 8, 256>>>(sgr, biasp, whh, sg, bih, bhh);

    dim3 gg(16, 16);
    // 6) Gbase GEMM + fused LSTM step 1 (c = 0); writes Gbase, c, h1
    tgemm_bf<0,4,1><<<gg, 256>>>(qg, DMV, BQ, wihh, wihl, 32,
                                 Gbase, NG, nullptr, 0, biasp, nullptr,
                                 qg, c, h1);
    // 7) steps 2..4 fused: gates = h_prev @ Whh_sel^T + Gbase + sgr -> LSTM -> h_next
    float* hin = h1; float* hout = h2;
    for (int s = 0; s < 3; s++) {
        tgemm_bf<0,4,2><<<gg, 256>>>(hin, DMV, BQ, whhh, whhl, 32,
                                     nullptr, NG, Gbase, NG, sgr, nullptr,
                                     qg, c, hout);
        float* tmp = hin; hin = hout; hout = tmp;
    }
    // 8) output cosine (hin holds the final h after the last swap)
    final_kernel<<<BQ / 8, 256>>>(out, hin, sgn);
}

// round 14
// speedup vs baseline: 1.1329x; 1.1329x over previous
#include <cuda_runtime.h>
#include <math.h>
#include <stdint.h>

#define VV   200000
#define BQ   2048
#define FF   5
#define NNB  64
#define KSEL 32
#define DD   256
#define DMV  512     // DM
#define HID  1024    // 2*DM
#define NG   2048    // packed gate cols, INTERLEAVED: col = j*4 + gate
#define MROWS (2*(BQ+FF))   // 4106 gcn rows
#define ER    (BQ + FF)     // 2053 encoder rows

// ---------------- static scratch ----------------
__device__ float g_meancat[(size_t)4224*2*DD];
__device__ float g_nb[(size_t)4224*DD];
__device__ float g_H[(size_t)2176*2*DMV];
__device__ float g_O[(size_t)2176*DMV];
__device__ float g_enc[(size_t)2176*DMV];
__device__ float g_sg[DMV];
__device__ float g_sgn[DMV];
__device__ float g_sgr[NG];
__device__ float g_biasp[NG];
__device__ float g_Gbase[(size_t)BQ*NG];
__device__ float g_c[BQ*DMV];
__device__ float g_h1[BQ*DMV];
__device__ float g_h2[BQ*DMV];

// packed bf16x2 weights (fragment order, k16 blocks): [pBlock128][kBlock16][1024]
__device__ unsigned g_wih_h[(size_t)16*32*1024],  g_wih_l[(size_t)16*32*1024];
__device__ unsigned g_whh_h[(size_t)16*32*1024],  g_whh_l[(size_t)16*32*1024];
__device__ unsigned g_p1w_h[(size_t)8*32*1024],   g_p1w_l[(size_t)8*32*1024];
__device__ unsigned g_p2w_h[(size_t)4*64*1024],   g_p2w_l[(size_t)4*64*1024];
__device__ unsigned g_gcnw_h[(size_t)2*32*1024],  g_gcnw_l[(size_t)2*32*1024];

// ---------------- helpers ----------------
__device__ __forceinline__ float warp_reduce_sum(float v) {
#pragma unroll
    for (int o = 16; o > 0; o >>= 1) v += __shfl_down_sync(0xffffffffu, v, o);
    return v;
}
__device__ __forceinline__ float sigmoidf_(float x) { return 1.0f / (1.0f + expf(-x)); }
__device__ __forceinline__ int clamp_id(int id) { return (id < 0 || id > VV) ? VV : id; }

__device__ __forceinline__ float block_reduce_256(float v, float* red) {
    int lane = threadIdx.x & 31, w = threadIdx.x >> 5;
    v = warp_reduce_sum(v);
    if (lane == 0) red[w] = v;
    __syncthreads();
    if (threadIdx.x == 0) {
        float s = 0.f;
#pragma unroll
        for (int i = 0; i < 8; i++) s += red[i];
        red[0] = s;
    }
    __syncthreads();
    float s = red[0];
    __syncthreads();
    return s;
}

__device__ __forceinline__ unsigned short f2bf(float x) {
    unsigned short r;
    asm("cvt.rn.bf16.f32 %0, %1;" : "=h"(r) : "f"(x));
    return r;
}
__device__ __forceinline__ float bf2f(unsigned short b) {
    return __uint_as_float((unsigned)b << 16);
}

__device__ __forceinline__ void mma_bf16(float* c, const unsigned* a, const unsigned* b) {
    asm volatile(
        "mma.sync.aligned.m16n8k16.row.col.f32.bf16.bf16.f32 "
        "{%0,%1,%2,%3}, {%4,%5,%6,%7}, {%8,%9}, {%0,%1,%2,%3};"
        : "+f"(c[0]), "+f"(c[1]), "+f"(c[2]), "+f"(c[3])
        : "r"(a[0]), "r"(a[1]), "r"(a[2]), "r"(a[3]), "r"(b[0]), "r"(b[1]));
}

__device__ __forceinline__ void cp16(unsigned* smem, const unsigned* g) {
    unsigned sa = (unsigned)__cvta_generic_to_shared(smem);
    asm volatile("cp.async.cg.shared.global [%0], [%1], 16;" :: "r"(sa), "l"(g));
}
__device__ __forceinline__ void cp_commit() { asm volatile("cp.async.commit_group;"); }
__device__ __forceinline__ void cp_wait0()  { asm volatile("cp.async.wait_group 0;"); }

// ---------------- weight pack: bf16x2 k16 fragment order ----------------
// gateHid==0: orig row = p*128 + col. gateHid!=0: gc = p*128+col -> row = (gc&3)*gateHid + (gc>>2)
__global__ __launch_bounds__(256) void packw16_kernel(
    const float* __restrict__ W, int ld, int gateHid,
    unsigned* __restrict__ ph, unsigned* __restrict__ pl)
{
    int kb = blockIdx.x, p = blockIdx.y, kBlocks = gridDim.x;
    unsigned* oh = ph + ((size_t)p * kBlocks + kb) * 1024;
    unsigned* ol = pl + ((size_t)p * kBlocks + kb) * 1024;
#pragma unroll
    for (int w = threadIdx.x; w < 1024; w += 256) {
        int nblk = w >> 6, rem = w & 63;
        int lane = rem >> 1, reg = rem & 1;
        int col = nblk * 8 + (lane >> 2);
        int k0 = reg * 8 + (lane & 3) * 2;
        int gc = p * 128 + col;
        int orow = gateHid ? ((gc & 3) * gateHid + (gc >> 2)) : gc;
        const float* wr = W + (size_t)orow * ld + kb * 16 + k0;
        float v0 = wr[0], v1 = wr[1];
        unsigned short h0 = f2bf(v0), h1 = f2bf(v1);
        unsigned short l0 = f2bf(v0 - bf2f(h0)), l1 = f2bf(v1 - bf2f(h1));
        oh[w] = (unsigned)h0 | ((unsigned)h1 << 16);
        ol[w] = (unsigned)l0 | ((unsigned)l1 << 16);
    }
}

// ---------------- neighbor encoder (R12 structure: small static smem, full occupancy) ----------------
__global__ __launch_bounds__(256) void nbenc_kernel(
    const int* __restrict__ query, const int* __restrict__ support,
    const int* __restrict__ qlc, const int* __restrict__ qrc,
    const int* __restrict__ slc, const int* __restrict__ srrc,
    const float* __restrict__ emb, float* __restrict__ meancat_out)
{
    int row = blockIdx.x, side = blockIdx.y;
    const int* conn; int id; int r;
    if (row < BQ) {
        conn = (side == 0 ? qlc : qrc) + row * NNB * 2;
        id   = query[row * 2 + side];
        r    = row * 2 + side;
    } else {
        int f = row - BQ;
        conn = (side == 0 ? slc : srrc) + f * NNB * 2;
        id   = support[f * 2 + side];
        r    = 2 * BQ + f * 2 + side;
    }
    id = clamp_id(id);
    int t = threadIdx.x, lane = t & 31, warp = t >> 5;

    __shared__ __align__(16) float csm[DD];
    __shared__ float sims[NNB];
    __shared__ int   sel[NNB];
    __shared__ float red[8];
    __shared__ float cn_s;

    float cv = emb[(size_t)id * DD + t];
    csm[t] = cv;
    float cs = block_reduce_256(cv * cv, red);
    if (t == 0) cn_s = sqrtf(cs);
    __syncthreads();

    float4 c0 = *(const float4*)&csm[lane * 8];
    float4 c1 = *(const float4*)&csm[lane * 8 + 4];

#pragma unroll
    for (int i = 0; i < 8; i++) {
        int n = warp * 8 + i;
        int eid = clamp_id(conn[n * 2 + 1]);
        const float4* er4 = (const float4*)(emb + (size_t)eid * DD);
        float4 e0 = er4[lane * 2];
        float4 e1 = er4[lane * 2 + 1];
        float dot = e0.x*c0.x + e0.y*c0.y + e0.z*c0.z + e0.w*c0.w
                  + e1.x*c1.x + e1.y*c1.y + e1.z*c1.z + e1.w*c1.w;
        float nn2 = e0.x*e0.x + e0.y*e0.y + e0.z*e0.z + e0.w*e0.w
                  + e1.x*e1.x + e1.y*e1.y + e1.z*e1.z + e1.w*e1.w;
        dot = warp_reduce_sum(dot);
        nn2 = warp_reduce_sum(nn2);
        if (lane == 0) sims[n] = dot / fmaxf(cn_s * sqrtf(nn2), 1e-8f);
    }
    __syncthreads();

    if (t < NNB) {
        float s = sims[t];
        int cnt = 0;
#pragma unroll
        for (int m = 0; m < NNB; m++) {
            float sm = sims[m];
            cnt += (sm > s) || (sm == s && m < t);
        }
        sel[t] = (cnt < KSEL);
    }
    __syncthreads();

    float accR = 0.f, accE = 0.f;
    for (int n = 0; n < NNB; n++) {
        if (!sel[n]) continue;
        int rid = clamp_id(conn[n * 2 + 0]);
        int eid = clamp_id(conn[n * 2 + 1]);
        accR += emb[(size_t)rid * DD + t];
        accE += emb[(size_t)eid * DD + t];
    }
    float* mc = meancat_out + (size_t)r * (2 * DD);
    mc[t]      = accR * (1.0f / KSEL);
    mc[DD + t] = accE * (1.0f / KSEL);
}

// ---------------- unified 3xBF16 GEMM: m16n8k16, 2 smem stages, cp.async B ----------------
// EPI: 0 = acc + v1 + addmat; 1 = tanh(acc+v1+v2); 2 = relu(acc+v1)
// LSTM: 0 = plain; 1 = Gbase+step1 (c=0; write C and c/h); 2 = step (addmat=Gbase; write c/h only)
template<int EPI, int MI, int LSTM>
__global__ __launch_bounds__(256, 2) void tgemm_bf(
    const float* __restrict__ A, int lda, int Mtot,
    const unsigned* __restrict__ Wh, const unsigned* __restrict__ Wl, int kBlocks,
    float* __restrict__ C, int ldc,
    const float* __restrict__ addmat, int ldm,
    const float* __restrict__ v1, const float* __restrict__ v2,
    const float* __restrict__ qg, float* __restrict__ cc, float* __restrict__ hh)
{
    constexpr int BM = MI * 32;                 // 64 or 128
    __shared__ unsigned Ash[2][BM * 8], Asl[2][BM * 8];
    __shared__ unsigned Bsh[2][1024], Bsl[2][1024];

    const int t = threadIdx.x;
    const int lane = t & 31, warp = t >> 5;
    const int wy = warp >> 2, wx = warp & 3;
    const int m0 = blockIdx.y * BM, n0 = blockIdx.x * 128;

    const unsigned* WH = Wh + (size_t)(n0 >> 7) * kBlocks * 1024;
    const unsigned* WL = Wl + (size_t)(n0 >> 7) * kBlocks * 1024;

    const bool astage = (t < BM * 2);
    const int row = t >> 1;
    const int kin = (t & 1) * 8;
    int ar = m0 + row; if (ar >= Mtot) ar = Mtot - 1;
    const float* Ap = A + (size_t)ar * lda + kin;
    const int baseA = (row >> 4) * 128 + (row & 7) * 16 + (((row & 15) >= 8) ? 1 : 0) + (kin ? 2 : 0);

    float acc[MI][4][4];
#pragma unroll
    for (int i = 0; i < MI; i++)
#pragma unroll
        for (int n = 0; n < 4; n++)
#pragma unroll
            for (int q = 0; q < 4; q++) acc[i][n][q] = 0.f;

    cp16(&Bsh[0][t * 4], WH + t * 4);
    cp16(&Bsl[0][t * 4], WL + t * 4);
    cp_commit();
    float4 va0, va1;
    if (astage) {
        va0 = *(const float4*)Ap;
        va1 = *(const float4*)(Ap + 4);
        float av[8] = {va0.x, va0.y, va0.z, va0.w, va1.x, va1.y, va1.z, va1.w};
#pragma unroll
        for (int j = 0; j < 4; j++) {
            unsigned short h0 = f2bf(av[2*j]),   h1 = f2bf(av[2*j+1]);
            unsigned short l0 = f2bf(av[2*j] - bf2f(h0));
            unsigned short l1 = f2bf(av[2*j+1] - bf2f(h1));
            Ash[0][baseA + j * 4] = (unsigned)h0 | ((unsigned)h1 << 16);
            Asl[0][baseA + j * 4] = (unsigned)l0 | ((unsigned)l1 << 16);
        }
    }
    cp_wait0();
    __syncthreads();

    int s = 0;
    for (int kb = 0; kb < kBlocks; kb++) {
        const bool more = (kb + 1 < kBlocks);
        if (more) {
            const unsigned* bh = WH + (size_t)(kb + 1) * 1024;
            const unsigned* bl = WL + (size_t)(kb + 1) * 1024;
            cp16(&Bsh[s ^ 1][t * 4], bh + t * 4);
            cp16(&Bsl[s ^ 1][t * 4], bl + t * 4);
            cp_commit();
            if (astage) {
                va0 = *(const float4*)(Ap + (kb + 1) * 16);
                va1 = *(const float4*)(Ap + (kb + 1) * 16 + 4);
            }
        }
        uint4 AH[MI], AL[MI];
        uint2 BH[4], BL[4];
#pragma unroll
        for (int i = 0; i < MI; i++) {
            int fi = (wy * MI + i) * 128 + lane * 4;
            AH[i] = *(const uint4*)&Ash[s][fi];
            AL[i] = *(const uint4*)&Asl[s][fi];
        }
#pragma unroll
        for (int n = 0; n < 4; n++) {
            int fn = (wx * 4 + n) * 64 + lane * 2;
            BH[n] = *(const uint2*)&Bsh[s][fn];
            BL[n] = *(const uint2*)&Bsl[s][fn];
        }
#pragma unroll
        for (int i = 0; i < MI; i++)
#pragma unroll
            for (int n = 0; n < 4; n++) {
                mma_bf16(acc[i][n], (const unsigned*)&AH[i], (const unsigned*)&BH[n]);
                mma_bf16(acc[i][n], (const unsigned*)&AL[i], (const unsigned*)&BH[n]);
                mma_bf16(acc[i][n], (const unsigned*)&AH[i], (const unsigned*)&BL[n]);
            }
        if (more) {
            if (astage) {
                float av[8] = {va0.x, va0.y, va0.z, va0.w, va1.x, va1.y, va1.z, va1.w};
#pragma unroll
                for (int j = 0; j < 4; j++) {
                    unsigned short h0 = f2bf(av[2*j]),   h1 = f2bf(av[2*j+1]);
                    unsigned short l0 = f2bf(av[2*j] - bf2f(h0));
                    unsigned short l1 = f2bf(av[2*j+1] - bf2f(h1));
                    Ash[s ^ 1][baseA + j * 4] = (unsigned)h0 | ((unsigned)h1 << 16);
                    Asl[s ^ 1][baseA + j * 4] = (unsigned)l0 | ((unsigned)l1 << 16);
                }
            }
            cp_wait0();
            __syncthreads();
            s ^= 1;
        }
    }

    // ---- epilogue ----
#pragma unroll
    for (int i = 0; i < MI; i++) {
#pragma unroll
        for (int n = 0; n < 4; n++) {
            int col = n0 + wx * 32 + n * 8 + (lane & 3) * 2;
            float v0 = 0.f, v1c = 0.f;
            if (v1) { v0 += v1[col]; v1c += v1[col + 1]; }
            if (EPI == 1 && v2) { v0 += v2[col]; v1c += v2[col + 1]; }
#pragma unroll
            for (int half = 0; half < 2; half++) {
                int m = m0 + wy * MI * 16 + i * 16 + (lane >> 2) + half * 8;
                float x0 = acc[i][n][half * 2 + 0] + v0;
                float x1 = acc[i][n][half * 2 + 1] + v1c;
                if (LSTM == 0) {
                    if (m >= Mtot) continue;
                    float* crow = C + (size_t)m * ldc + col;
                    if (EPI == 1) {
                        crow[0] = tanhf(x0); crow[1] = tanhf(x1);
                    } else if (EPI == 2) {
                        crow[0] = fmaxf(x0, 0.f); crow[1] = fmaxf(x1, 0.f);
                    } else {
                        if (addmat) {
                            const float* mr = addmat + (size_t)m * ldm + col;
                            x0 += mr[0]; x1 += mr[1];
                        }
                        crow[0] = x0; crow[1] = x1;
                    }
                } else {
                    // interleaved gates: col = j*4+g. Quad lanes: even holds (i,f), odd holds (g,o).
                    if (LSTM == 2) {
                        const float* mr = addmat + (size_t)m * ldm + col;
                        x0 += mr[0]; x1 += mr[1];
                    } else {
                        float* crow = C + (size_t)m * ldc + col;   // Gbase
                        crow[0] = x0; crow[1] = x1;
                    }
                    float y0 = __shfl_xor_sync(0xffffffffu, x0, 1);
                    float y1 = __shfl_xor_sync(0xffffffffu, x1, 1);
                    if ((lane & 1) == 0) {
                        int j = col >> 2;
                        int idx = m * DMV + j;
                        float cn = sigmoidf_(x0) * tanhf(y0);          // sig(i)*tanh(g)
                        if (LSTM == 2) cn += sigmoidf_(x1) * cc[idx];  // + sig(f)*c
                        cc[idx] = cn;
                        hh[idx] = qg[idx] + sigmoidf_(y1) * tanhf(cn); // qg + sig(o)*tanh(c)
                    }
                }
            }
        }
    }
}

// ---------------- LayerNorm over 512 per row ----------------
__global__ __launch_bounds__(256) void ln_kernel(
    const float* __restrict__ O, float* __restrict__ Y,
    const float* __restrict__ lng, const float* __restrict__ lnb)
{
    int row = blockIdx.x, t = threadIdx.x;
    __shared__ float red[8];
    float o0 = O[(size_t)row * DMV + t];
    float o1 = O[(size_t)row * DMV + t + 256];
    float msum = block_reduce_256(o0 + o1, red);
    float m = msum * (1.0f / DMV);
    float d0 = o0 - m, d1 = o1 - m;
    float vsum = block_reduce_256(d0 * d0 + d1 * d1, red);
    float rstd = rsqrtf(vsum * (1.0f / DMV) + 1e-5f);
    Y[(size_t)row * DMV + t]       = d0 * rstd * lng[t]       + lnb[t];
    Y[(size_t)row * DMV + t + 256] = d1 * rstd * lng[t + 256] + lnb[t + 256];
}

// ---------------- mean over F support rows + normalized copy ----------------
__global__ void avgnorm_kernel(float* __restrict__ sg, float* __restrict__ sgn,
                               const float* __restrict__ senc)
{
    int t = threadIdx.x; // 512 threads
    __shared__ float red[16];
    float s = 0.f;
#pragma unroll
    for (int f = 0; f < FF; f++) s += senc[f * DMV + t];
    s *= (1.0f / FF);
    sg[t] = s;
    int lane = t & 31, w = t >> 5;
    float v = warp_reduce_sum(s * s);
    if (lane == 0) red[w] = v;
    __syncthreads();
    if (t == 0) {
        float tot = 0.f;
#pragma unroll
        for (int i = 0; i < 16; i++) tot += red[i];
        red[0] = sqrtf(tot);
    }
    __syncthreads();
    float nrm = red[0];
    sgn[t] = s / fmaxf(nrm, 1e-12f);
}

// ---------------- packed constants: sgr[n], biasp[n] (interleaved: n = j*4+g) ----------------
__global__ __launch_bounds__(256) void pack_kernel(
    float* __restrict__ sgr, float* __restrict__ biasp,
    const float* __restrict__ whh, const float* __restrict__ sg,
    const float* __restrict__ bih, const float* __restrict__ bhh)
{
    int n = (blockIdx.x * blockDim.x + threadIdx.x) >> 5;
    int lane = threadIdx.x & 31;
    if (n >= NG) return;
    int jf = (n & 3) * HID + (n >> 2);
    const float* wr = whh + (size_t)jf * HID + DMV;
    float a = 0.f;
#pragma unroll
    for (int k = lane; k < DMV; k += 32) a += wr[k] * sg[k];
    a = warp_reduce_sum(a);
    if (lane == 0) {
        sgr[n] = a;
        biasp[n] = bih[jf] + bhh[jf];
    }
}

// ---------------- final cosine output ----------------
__global__ __launch_bounds__(256) void final_kernel(
    float* __restrict__ out, const float* __restrict__ h,
    const float* __restrict__ sgn)
{
    int b = (blockIdx.x * blockDim.x + threadIdx.x) >> 5;
    int lane = threadIdx.x & 31;
    if (b >= BQ) return;
    float nn = 0.f, dd = 0.f;
#pragma unroll
    for (int d = lane; d < DMV; d += 32) {
        float hv = h[(size_t)b * DMV + d];
        nn += hv * hv;
        dd += hv * sgn[d];
    }
    nn = warp_reduce_sum(nn);
    dd = warp_reduce_sum(dd);
    if (lane == 0) out[b] = dd / fmaxf(sqrtf(nn), 1e-12f);
}

// ---------------- input binding ----------------
enum {
    R_query=0, R_support, R_qlc, R_qld, R_qrc, R_qrd, R_slc, R_sld, R_src, R_srd,
    R_emb, R_gcnw, R_gcnwb, R_gcnb, R_p1w, R_p1b, R_p2w, R_p2b, R_lng, R_lnb,
    R_wih, R_whh, R_bih, R_bhh, R_COUNT
};
static const int DICT_SIZES[R_COUNT] = {
    4096, 10, 262144, 2048, 262144, 2048, 640, 5, 640, 5,
    51200256, 131072, 256, 256, 524288, 1024, 524288, 512, 512, 512,
    2097152, 4194304, 4096, 4096
};
static bool sizes_match(const int* s, const int* exp, int n) {
    for (int i = 0; i < n; i++) if (s[i] != exp[i]) return false;
    return true;
}

// ---------------- launcher ----------------
extern "C" void kernel_launch(void* const* d_in, const int* in_sizes, int n_in,
                              void* d_out, int out_size)
{
    int map[R_COUNT];
    if (n_in >= R_COUNT && sizes_match(in_sizes, DICT_SIZES, R_COUNT)) {
        for (int r = 0; r < R_COUNT; r++) map[r] = r;
    } else {
        bool used[64] = {false};
        for (int r = 0; r < R_COUNT; r++) {
            map[r] = 0;
            for (int i = 0; i < n_in && i < 64; i++) {
                if (!used[i] && in_sizes[i] == DICT_SIZES[r]) { map[r] = i; used[i] = true; break; }
            }
        }
    }

    const int*   query   = (const int*)d_in[map[R_query]];
    const int*   support = (const int*)d_in[map[R_support]];
    const int*   qlc     = (const int*)d_in[map[R_qlc]];
    const int*   qrc     = (const int*)d_in[map[R_qrc]];
    const int*   slc     = (const int*)d_in[map[R_slc]];
    const int*   srrc    = (const int*)d_in[map[R_src]];
    const float* emb     = (const float*)d_in[map[R_emb]];
    const float* gcnw    = (const float*)d_in[map[R_gcnw]];
    const float* gcnwb   = (const float*)d_in[map[R_gcnwb]];
    const float* gcnb    = (const float*)d_in[map[R_gcnb]];
    const float* p1w     = (const float*)d_in[map[R_p1w]];
    const float* p1b     = (const float*)d_in[map[R_p1b]];
    const float* p2w     = (const float*)d_in[map[R_p2w]];
    const float* p2b     = (const float*)d_in[map[R_p2b]];
    const float* lng     = (const float*)d_in[map[R_lng]];
    const float* lnb     = (const float*)d_in[map[R_lnb]];
    const float* wih     = (const float*)d_in[map[R_wih]];
    const float* whh     = (const float*)d_in[map[R_whh]];
    const float* bih     = (const float*)d_in[map[R_bih]];
    const float* bhh     = (const float*)d_in[map[R_bhh]];
    float* out = (float*)d_out;

    float *mc, *nb, *H, *O, *enc, *sg, *sgn, *sgr, *biasp, *Gbase, *c, *h1, *h2;
    cudaGetSymbolAddress((void**)&mc,    g_meancat);
    cudaGetSymbolAddress((void**)&nb,    g_nb);
    cudaGetSymbolAddress((void**)&H,     g_H);
    cudaGetSymbolAddress((void**)&O,     g_O);
    cudaGetSymbolAddress((void**)&enc,   g_enc);
    cudaGetSymbolAddress((void**)&sg,    g_sg);
    cudaGetSymbolAddress((void**)&sgn,   g_sgn);
    cudaGetSymbolAddress((void**)&sgr,   g_sgr);
    cudaGetSymbolAddress((void**)&biasp, g_biasp);
    cudaGetSymbolAddress((void**)&Gbase, g_Gbase);
    cudaGetSymbolAddress((void**)&c,     g_c);
    cudaGetSymbolAddress((void**)&h1,    g_h1);
    cudaGetSymbolAddress((void**)&h2,    g_h2);

    unsigned *wihh, *wihl, *whhh, *whhl, *p1h, *p1l, *p2h, *p2l, *gch, *gcl;
    cudaGetSymbolAddress((void**)&wihh, g_wih_h);  cudaGetSymbolAddress((void**)&wihl, g_wih_l);
    cudaGetSymbolAddress((void**)&whhh, g_whh_h);  cudaGetSymbolAddress((void**)&whhl, g_whh_l);
    cudaGetSymbolAddress((void**)&p1h,  g_p1w_h);  cudaGetSymbolAddress((void**)&p1l,  g_p1w_l);
    cudaGetSymbolAddress((void**)&p2h,  g_p2w_h);  cudaGetSymbolAddress((void**)&p2l,  g_p2w_l);
    cudaGetSymbolAddress((void**)&gch,  g_gcnw_h); cudaGetSymbolAddress((void**)&gcl,  g_gcnw_l);

    float* qg   = enc;
    float* senc = enc + (size_t)BQ * DMV;

    // 0) pack weights (bf16x2 hi/lo, k16 fragment order; gates interleaved)
    packw16_kernel<<<dim3(32, 2),  256>>>(gcnw, 512,  0,    gch,  gcl);
    packw16_kernel<<<dim3(32, 8),  256>>>(p1w,  512,  0,    p1h,  p1l);
    packw16_kernel<<<dim3(64, 4),  256>>>(p2w,  1024, 0,    p2h,  p2l);
    packw16_kernel<<<dim3(32, 16), 256>>>(wih,  512,  HID,  wihh, wihl);
    packw16_kernel<<<dim3(32, 16), 256>>>(whh,  1024, HID,  whhh, whhl);

    // 1) neighbor top-K means -> meancat (4106 x 512)
    nbenc_kernel<<<dim3(BQ + FF, 2), 256>>>(query, support, qlc, qrc, slc, srrc, emb, mc);
    // 2) GCN: nb = tanh(mc @ gcnw^T + wb + b)
    tgemm_bf<1,2,0><<<dim3(2, 65), 256>>>(mc, 2*DD, MROWS, gch, gcl, 32,
                                          nb, DD, nullptr, 0, gcnwb, gcnb,
                                          nullptr, nullptr, nullptr);
    // 3) encoder batched over 2053 rows
    tgemm_bf<2,2,0><<<dim3(8, 33), 256>>>(nb, DMV, ER, p1h, p1l, 32,
                                          H, 2*DMV, nullptr, 0, p1b, nullptr,
                                          nullptr, nullptr, nullptr);
    tgemm_bf<0,2,0><<<dim3(4, 33), 256>>>(H, 2*DMV, ER, p2h, p2l, 64,
                                          O, DMV, nb, DMV, p2b, nullptr,
                                          nullptr, nullptr, nullptr);
    ln_kernel<<<ER, 256>>>(O, enc, lng, lnb);
    // 4) support_g mean + normalized copy
    avgnorm_kernel<<<1, 512>>>(sg, sgn, senc);
    // 5) packed sgr + bias (interleaved)
    pack_kernel<<<NG / 8, 256>>>(sgr, biasp, whh, sg, bih, bhh);

    dim3 gg(16, 16);
    // 6) Gbase GEMM + fused LSTM step 1 (c = 0); writes Gbase, c, h1
    tgemm_bf<0,4,1><<<gg, 256>>>(qg, DMV, BQ, wihh, wihl, 32,
                                 Gbase, NG, nullptr, 0, biasp, nullptr,
                                 qg, c, h1);
    // 7) steps 2..4 fused: gates = h_prev @ Whh_sel^T + Gbase + sgr -> LSTM -> h_next
    float* hin = h1; float* hout = h2;
    for (int s = 0; s < 3; s++) {
        tgemm_bf<0,4,2><<<gg, 256>>>(hin, DMV, BQ, whhh, whhl, 32,
                                     nullptr, NG, Gbase, NG, sgr, nullptr,
                                     qg, c, hout);
        float* tmp = hin; hin = hout; hout = tmp;
    }
    // 8) output cosine (hin holds the final h after the last swap)
    final_kernel<<<BQ / 8, 256>>>(out, hin, sgn);
}

// round 15
// speedup vs baseline: 1.1345x; 1.0014x over previous
#include <cuda_runtime.h>
#include <math.h>
#include <stdint.h>

#define VV   200000
#define BQ   2048
#define FF   5
#define NNB  64
#define KSEL 32
#define DD   256
#define DMV  512     // DM
#define HID  1024    // 2*DM
#define NG   2048    // packed gate cols, INTERLEAVED: col = j*4 + gate
#define MROWS (2*(BQ+FF))   // 4106 gcn rows
#define ER    (BQ + FF)     // 2053 encoder rows

// ---------------- static scratch ----------------
__device__ float g_meancat[(size_t)4224*2*DD];
__device__ float g_nb[(size_t)4224*DD];
__device__ float g_H[(size_t)2176*2*DMV];
__device__ float g_O[(size_t)2176*DMV];
__device__ float g_enc[(size_t)2176*DMV];
__device__ float g_sg[DMV];
__device__ float g_sgn[DMV];
__device__ float g_sgr[NG];
__device__ float g_biasp[NG];
__device__ float g_Gbase[(size_t)BQ*NG];
__device__ float g_c[BQ*DMV];
__device__ float g_h1[BQ*DMV];
__device__ float g_h2[BQ*DMV];

// packed bf16x2 weights (fragment order, k16 blocks): [pBlock128][kBlock16][1024]
__device__ unsigned g_wih_h[(size_t)16*32*1024],  g_wih_l[(size_t)16*32*1024];
__device__ unsigned g_whh_h[(size_t)16*32*1024],  g_whh_l[(size_t)16*32*1024];
__device__ unsigned g_p1w_h[(size_t)8*32*1024],   g_p1w_l[(size_t)8*32*1024];
__device__ unsigned g_p2w_h[(size_t)4*64*1024],   g_p2w_l[(size_t)4*64*1024];
__device__ unsigned g_gcnw_h[(size_t)2*32*1024],  g_gcnw_l[(size_t)2*32*1024];

// ---------------- helpers ----------------
__device__ __forceinline__ float warp_reduce_sum(float v) {
#pragma unroll
    for (int o = 16; o > 0; o >>= 1) v += __shfl_down_sync(0xffffffffu, v, o);
    return v;
}
__device__ __forceinline__ float sigmoidf_(float x) { return 1.0f / (1.0f + expf(-x)); }
__device__ __forceinline__ int clamp_id(int id) { return (id < 0 || id > VV) ? VV : id; }

__device__ __forceinline__ float block_reduce_256(float v, float* red) {
    int lane = threadIdx.x & 31, w = threadIdx.x >> 5;
    v = warp_reduce_sum(v);
    if (lane == 0) red[w] = v;
    __syncthreads();
    if (threadIdx.x == 0) {
        float s = 0.f;
#pragma unroll
        for (int i = 0; i < 8; i++) s += red[i];
        red[0] = s;
    }
    __syncthreads();
    float s = red[0];
    __syncthreads();
    return s;
}

__device__ __forceinline__ unsigned short f2bf(float x) {
    unsigned short r;
    asm("cvt.rn.bf16.f32 %0, %1;" : "=h"(r) : "f"(x));
    return r;
}
__device__ __forceinline__ float bf2f(unsigned short b) {
    return __uint_as_float((unsigned)b << 16);
}

__device__ __forceinline__ void mma_bf16(float* c, const unsigned* a, const unsigned* b) {
    asm volatile(
        "mma.sync.aligned.m16n8k16.row.col.f32.bf16.bf16.f32 "
        "{%0,%1,%2,%3}, {%4,%5,%6,%7}, {%8,%9}, {%0,%1,%2,%3};"
        : "+f"(c[0]), "+f"(c[1]), "+f"(c[2]), "+f"(c[3])
        : "r"(a[0]), "r"(a[1]), "r"(a[2]), "r"(a[3]), "r"(b[0]), "r"(b[1]));
}

__device__ __forceinline__ void cp16(unsigned* smem, const unsigned* g) {
    unsigned sa = (unsigned)__cvta_generic_to_shared(smem);
    asm volatile("cp.async.cg.shared.global [%0], [%1], 16;" :: "r"(sa), "l"(g));
}
__device__ __forceinline__ void cp_commit() { asm volatile("cp.async.commit_group;"); }
__device__ __forceinline__ void cp_wait0()  { asm volatile("cp.async.wait_group 0;"); }

// ---------------- weight pack: bf16x2 k16 fragment order ----------------
// gateHid==0: orig row = p*128 + col. gateHid!=0: gc = p*128+col -> row = (gc&3)*gateHid + (gc>>2)
__global__ __launch_bounds__(256) void packw16_kernel(
    const float* __restrict__ W, int ld, int gateHid,
    unsigned* __restrict__ ph, unsigned* __restrict__ pl)
{
    int kb = blockIdx.x, p = blockIdx.y, kBlocks = gridDim.x;
    unsigned* oh = ph + ((size_t)p * kBlocks + kb) * 1024;
    unsigned* ol = pl + ((size_t)p * kBlocks + kb) * 1024;
#pragma unroll
    for (int w = threadIdx.x; w < 1024; w += 256) {
        int nblk = w >> 6, rem = w & 63;
        int lane = rem >> 1, reg = rem & 1;
        int col = nblk * 8 + (lane >> 2);
        int k0 = reg * 8 + (lane & 3) * 2;
        int gc = p * 128 + col;
        int orow = gateHid ? ((gc & 3) * gateHid + (gc >> 2)) : gc;
        const float* wr = W + (size_t)orow * ld + kb * 16 + k0;
        float v0 = wr[0], v1 = wr[1];
        unsigned short h0 = f2bf(v0), h1 = f2bf(v1);
        unsigned short l0 = f2bf(v0 - bf2f(h0)), l1 = f2bf(v1 - bf2f(h1));
        oh[w] = (unsigned)h0 | ((unsigned)h1 << 16);
        ol[w] = (unsigned)l0 | ((unsigned)l1 << 16);
    }
}

// ---------------- neighbor encoder (R12 structure: small static smem, full occupancy) ----------------
__global__ __launch_bounds__(256) void nbenc_kernel(
    const int* __restrict__ query, const int* __restrict__ support,
    const int* __restrict__ qlc, const int* __restrict__ qrc,
    const int* __restrict__ slc, const int* __restrict__ srrc,
    const float* __restrict__ emb, float* __restrict__ meancat_out)
{
    int row = blockIdx.x, side = blockIdx.y;
    const int* conn; int id; int r;
    if (row < BQ) {
        conn = (side == 0 ? qlc : qrc) + row * NNB * 2;
        id   = query[row * 2 + side];
        r    = row * 2 + side;
    } else {
        int f = row - BQ;
        conn = (side == 0 ? slc : srrc) + f * NNB * 2;
        id   = support[f * 2 + side];
        r    = 2 * BQ + f * 2 + side;
    }
    id = clamp_id(id);
    int t = threadIdx.x, lane = t & 31, warp = t >> 5;

    __shared__ __align__(16) float csm[DD];
    __shared__ float sims[NNB];
    __shared__ int   sel[NNB];
    __shared__ float red[8];
    __shared__ float cn_s;

    float cv = emb[(size_t)id * DD + t];
    csm[t] = cv;
    float cs = block_reduce_256(cv * cv, red);
    if (t == 0) cn_s = sqrtf(cs);
    __syncthreads();

    float4 c0 = *(const float4*)&csm[lane * 8];
    float4 c1 = *(const float4*)&csm[lane * 8 + 4];

#pragma unroll
    for (int i = 0; i < 8; i++) {
        int n = warp * 8 + i;
        int eid = clamp_id(conn[n * 2 + 1]);
        const float4* er4 = (const float4*)(emb + (size_t)eid * DD);
        float4 e0 = er4[lane * 2];
        float4 e1 = er4[lane * 2 + 1];
        float dot = e0.x*c0.x + e0.y*c0.y + e0.z*c0.z + e0.w*c0.w
                  + e1.x*c1.x + e1.y*c1.y + e1.z*c1.z + e1.w*c1.w;
        float nn2 = e0.x*e0.x + e0.y*e0.y + e0.z*e0.z + e0.w*e0.w
                  + e1.x*e1.x + e1.y*e1.y + e1.z*e1.z + e1.w*e1.w;
        dot = warp_reduce_sum(dot);
        nn2 = warp_reduce_sum(nn2);
        if (lane == 0) sims[n] = dot / fmaxf(cn_s * sqrtf(nn2), 1e-8f);
    }
    __syncthreads();

    if (t < NNB) {
        float s = sims[t];
        int cnt = 0;
#pragma unroll
        for (int m = 0; m < NNB; m++) {
            float sm = sims[m];
            cnt += (sm > s) || (sm == s && m < t);
        }
        sel[t] = (cnt < KSEL);
    }
    __syncthreads();

    float accR = 0.f, accE = 0.f;
    for (int n = 0; n < NNB; n++) {
        if (!sel[n]) continue;
        int rid = clamp_id(conn[n * 2 + 0]);
        int eid = clamp_id(conn[n * 2 + 1]);
        accR += emb[(size_t)rid * DD + t];
        accE += emb[(size_t)eid * DD + t];
    }
    float* mc = meancat_out + (size_t)r * (2 * DD);
    mc[t]      = accR * (1.0f / KSEL);
    mc[DD + t] = accE * (1.0f / KSEL);
}

// ---------------- unified 3xBF16 GEMM: m16n8k16, 2 smem stages, cp.async B ----------------
// EPI: 0 = acc + v1 + addmat; 1 = tanh(acc+v1+v2); 2 = relu(acc+v1)
// LSTM: 0 = plain; 1 = Gbase+step1 (c=0; write C and c/h); 2 = step (addmat=Gbase; write c/h only)
template<int EPI, int MI, int LSTM>
__global__ __launch_bounds__(256, 2) void tgemm_bf(
    const float* __restrict__ A, int lda, int Mtot,
    const unsigned* __restrict__ Wh, const unsigned* __restrict__ Wl, int kBlocks,
    float* __restrict__ C, int ldc,
    const float* __restrict__ addmat, int ldm,
    const float* __restrict__ v1, const float* __restrict__ v2,
    const float* __restrict__ qg, float* __restrict__ cc, float* __restrict__ hh)
{
    constexpr int BM = MI * 32;                 // 64 or 128
    __shared__ unsigned Ash[2][BM * 8], Asl[2][BM * 8];
    __shared__ unsigned Bsh[2][1024], Bsl[2][1024];

    const int t = threadIdx.x;
    const int lane = t & 31, warp = t >> 5;
    const int wy = warp >> 2, wx = warp & 3;
    const int m0 = blockIdx.y * BM, n0 = blockIdx.x * 128;

    const unsigned* WH = Wh + (size_t)(n0 >> 7) * kBlocks * 1024;
    const unsigned* WL = Wl + (size_t)(n0 >> 7) * kBlocks * 1024;

    const bool astage = (t < BM * 2);
    const int row = t >> 1;
    const int kin = (t & 1) * 8;
    int ar = m0 + row; if (ar >= Mtot) ar = Mtot - 1;
    const float* Ap = A + (size_t)ar * lda + kin;
    const int baseA = (row >> 4) * 128 + (row & 7) * 16 + (((row & 15) >= 8) ? 1 : 0) + (kin ? 2 : 0);

    float acc[MI][4][4];
#pragma unroll
    for (int i = 0; i < MI; i++)
#pragma unroll
        for (int n = 0; n < 4; n++)
#pragma unroll
            for (int q = 0; q < 4; q++) acc[i][n][q] = 0.f;

    cp16(&Bsh[0][t * 4], WH + t * 4);
    cp16(&Bsl[0][t * 4], WL + t * 4);
    cp_commit();
    float4 va0, va1;
    if (astage) {
        va0 = *(const float4*)Ap;
        va1 = *(const float4*)(Ap + 4);
        float av[8] = {va0.x, va0.y, va0.z, va0.w, va1.x, va1.y, va1.z, va1.w};
#pragma unroll
        for (int j = 0; j < 4; j++) {
            unsigned short h0 = f2bf(av[2*j]),   h1 = f2bf(av[2*j+1]);
            unsigned short l0 = f2bf(av[2*j] - bf2f(h0));
            unsigned short l1 = f2bf(av[2*j+1] - bf2f(h1));
            Ash[0][baseA + j * 4] = (unsigned)h0 | ((unsigned)h1 << 16);
            Asl[0][baseA + j * 4] = (unsigned)l0 | ((unsigned)l1 << 16);
        }
    }
    cp_wait0();
    __syncthreads();

    int s = 0;
    for (int kb = 0; kb < kBlocks; kb++) {
        const bool more = (kb + 1 < kBlocks);
        if (more) {
            const unsigned* bh = WH + (size_t)(kb + 1) * 1024;
            const unsigned* bl = WL + (size_t)(kb + 1) * 1024;
            cp16(&Bsh[s ^ 1][t * 4], bh + t * 4);
            cp16(&Bsl[s ^ 1][t * 4], bl + t * 4);
            cp_commit();
            if (astage) {
                va0 = *(const float4*)(Ap + (kb + 1) * 16);
                va1 = *(const float4*)(Ap + (kb + 1) * 16 + 4);
            }
        }
        uint4 AH[MI], AL[MI];
        uint2 BH[4], BL[4];
#pragma unroll
        for (int i = 0; i < MI; i++) {
            int fi = (wy * MI + i) * 128 + lane * 4;
            AH[i] = *(const uint4*)&Ash[s][fi];
            AL[i] = *(const uint4*)&Asl[s][fi];
        }
#pragma unroll
        for (int n = 0; n < 4; n++) {
            int fn = (wx * 4 + n) * 64 + lane * 2;
            BH[n] = *(const uint2*)&Bsh[s][fn];
            BL[n] = *(const uint2*)&Bsl[s][fn];
        }
#pragma unroll
        for (int i = 0; i < MI; i++)
#pragma unroll
            for (int n = 0; n < 4; n++) {
                mma_bf16(acc[i][n], (const unsigned*)&AH[i], (const unsigned*)&BH[n]);
                mma_bf16(acc[i][n], (const unsigned*)&AL[i], (const unsigned*)&BH[n]);
                mma_bf16(acc[i][n], (const unsigned*)&AH[i], (const unsigned*)&BL[n]);
            }
        if (more) {
            if (astage) {
                float av[8] = {va0.x, va0.y, va0.z, va0.w, va1.x, va1.y, va1.z, va1.w};
#pragma unroll
                for (int j = 0; j < 4; j++) {
                    unsigned short h0 = f2bf(av[2*j]),   h1 = f2bf(av[2*j+1]);
                    unsigned short l0 = f2bf(av[2*j] - bf2f(h0));
                    unsigned short l1 = f2bf(av[2*j+1] - bf2f(h1));
                    Ash[s ^ 1][baseA + j * 4] = (unsigned)h0 | ((unsigned)h1 << 16);
                    Asl[s ^ 1][baseA + j * 4] = (unsigned)l0 | ((unsigned)l1 << 16);
                }
            }
            cp_wait0();
            __syncthreads();
            s ^= 1;
        }
    }

    // ---- epilogue ----
#pragma unroll
    for (int i = 0; i < MI; i++) {
#pragma unroll
        for (int n = 0; n < 4; n++) {
            int col = n0 + wx * 32 + n * 8 + (lane & 3) * 2;
            float v0 = 0.f, v1c = 0.f;
            if (v1) { v0 += v1[col]; v1c += v1[col + 1]; }
            if (EPI == 1 && v2) { v0 += v2[col]; v1c += v2[col + 1]; }
#pragma unroll
            for (int half = 0; half < 2; half++) {
                int m = m0 + wy * MI * 16 + i * 16 + (lane >> 2) + half * 8;
                float x0 = acc[i][n][half * 2 + 0] + v0;
                float x1 = acc[i][n][half * 2 + 1] + v1c;
                if (LSTM == 0) {
                    if (m >= Mtot) continue;
                    float* crow = C + (size_t)m * ldc + col;
                    if (EPI == 1) {
                        crow[0] = tanhf(x0); crow[1] = tanhf(x1);
                    } else if (EPI == 2) {
                        crow[0] = fmaxf(x0, 0.f); crow[1] = fmaxf(x1, 0.f);
                    } else {
                        if (addmat) {
                            const float* mr = addmat + (size_t)m * ldm + col;
                            x0 += mr[0]; x1 += mr[1];
                        }
                        crow[0] = x0; crow[1] = x1;
                    }
                } else {
                    // interleaved gates: col = j*4+g. Quad lanes: even holds (i,f), odd holds (g,o).
                    if (LSTM == 2) {
                        const float* mr = addmat + (size_t)m * ldm + col;
                        x0 += mr[0]; x1 += mr[1];
                    } else {
                        float* crow = C + (size_t)m * ldc + col;   // Gbase
                        crow[0] = x0; crow[1] = x1;
                    }
                    float y0 = __shfl_xor_sync(0xffffffffu, x0, 1);
                    float y1 = __shfl_xor_sync(0xffffffffu, x1, 1);
                    if ((lane & 1) == 0) {
                        int j = col >> 2;
                        int idx = m * DMV + j;
                        float cn = sigmoidf_(x0) * tanhf(y0);          // sig(i)*tanh(g)
                        if (LSTM == 2) cn += sigmoidf_(x1) * cc[idx];  // + sig(f)*c
                        cc[idx] = cn;
                        hh[idx] = qg[idx] + sigmoidf_(y1) * tanhf(cn); // qg + sig(o)*tanh(c)
                    }
                }
            }
        }
    }
}

// ---------------- LayerNorm over 512 per row ----------------
__global__ __launch_bounds__(256) void ln_kernel(
    const float* __restrict__ O, float* __restrict__ Y,
    const float* __restrict__ lng, const float* __restrict__ lnb)
{
    int row = blockIdx.x, t = threadIdx.x;
    __shared__ float red[8];
    float o0 = O[(size_t)row * DMV + t];
    float o1 = O[(size_t)row * DMV + t + 256];
    float msum = block_reduce_256(o0 + o1, red);
    float m = msum * (1.0f / DMV);
    float d0 = o0 - m, d1 = o1 - m;
    float vsum = block_reduce_256(d0 * d0 + d1 * d1, red);
    float rstd = rsqrtf(vsum * (1.0f / DMV) + 1e-5f);
    Y[(size_t)row * DMV + t]       = d0 * rstd * lng[t]       + lnb[t];
    Y[(size_t)row * DMV + t + 256] = d1 * rstd * lng[t + 256] + lnb[t + 256];
}

// ---------------- mean over F support rows + normalized copy ----------------
__global__ void avgnorm_kernel(float* __restrict__ sg, float* __restrict__ sgn,
                               const float* __restrict__ senc)
{
    int t = threadIdx.x; // 512 threads
    __shared__ float red[16];
    float s = 0.f;
#pragma unroll
    for (int f = 0; f < FF; f++) s += senc[f * DMV + t];
    s *= (1.0f / FF);
    sg[t] = s;
    int lane = t & 31, w = t >> 5;
    float v = warp_reduce_sum(s * s);
    if (lane == 0) red[w] = v;
    __syncthreads();
    if (t == 0) {
        float tot = 0.f;
#pragma unroll
        for (int i = 0; i < 16; i++) tot += red[i];
        red[0] = sqrtf(tot);
    }
    __syncthreads();
    float nrm = red[0];
    sgn[t] = s / fmaxf(nrm, 1e-12f);
}

// ---------------- packed constants: sgr[n], biasp[n] (interleaved: n = j*4+g) ----------------
__global__ __launch_bounds__(256) void pack_kernel(
    float* __restrict__ sgr, float* __restrict__ biasp,
    const float* __restrict__ whh, const float* __restrict__ sg,
    const float* __restrict__ bih, const float* __restrict__ bhh)
{
    int n = (blockIdx.x * blockDim.x + threadIdx.x) >> 5;
    int lane = threadIdx.x & 31;
    if (n >= NG) return;
    int jf = (n & 3) * HID + (n >> 2);
    const float* wr = whh + (size_t)jf * HID + DMV;
    float a = 0.f;
#pragma unroll
    for (int k = lane; k < DMV; k += 32) a += wr[k] * sg[k];
    a = warp_reduce_sum(a);
    if (lane == 0) {
        sgr[n] = a;
        biasp[n] = bih[jf] + bhh[jf];
    }
}

// ---------------- final cosine output ----------------
__global__ __launch_bounds__(256) void final_kernel(
    float* __restrict__ out, const float* __restrict__ h,
    const float* __restrict__ sgn)
{
    int b = (blockIdx.x * blockDim.x + threadIdx.x) >> 5;
    int lane = threadIdx.x & 31;
    if (b >= BQ) return;
    float nn = 0.f, dd = 0.f;
#pragma unroll
    for (int d = lane; d < DMV; d += 32) {
        float hv = h[(size_t)b * DMV + d];
        nn += hv * hv;
        dd += hv * sgn[d];
    }
    nn = warp_reduce_sum(nn);
    dd = warp_reduce_sum(dd);
    if (lane == 0) out[b] = dd / fmaxf(sqrtf(nn), 1e-12f);
}

// ---------------- input binding ----------------
enum {
    R_query=0, R_support, R_qlc, R_qld, R_qrc, R_qrd, R_slc, R_sld, R_src, R_srd,
    R_emb, R_gcnw, R_gcnwb, R_gcnb, R_p1w, R_p1b, R_p2w, R_p2b, R_lng, R_lnb,
    R_wih, R_whh, R_bih, R_bhh, R_COUNT
};
static const int DICT_SIZES[R_COUNT] = {
    4096, 10, 262144, 2048, 262144, 2048, 640, 5, 640, 5,
    51200256, 131072, 256, 256, 524288, 1024, 524288, 512, 512, 512,
    2097152, 4194304, 4096, 4096
};
static bool sizes_match(const int* s, const int* exp, int n) {
    for (int i = 0; i < n; i++) if (s[i] != exp[i]) return false;
    return true;
}

// ---------------- launcher ----------------
extern "C" void kernel_launch(void* const* d_in, const int* in_sizes, int n_in,
                              void* d_out, int out_size)
{
    int map[R_COUNT];
    if (n_in >= R_COUNT && sizes_match(in_sizes, DICT_SIZES, R_COUNT)) {
        for (int r = 0; r < R_COUNT; r++) map[r] = r;
    } else {
        bool used[64] = {false};
        for (int r = 0; r < R_COUNT; r++) {
            map[r] = 0;
            for (int i = 0; i < n_in && i < 64; i++) {
                if (!used[i] && in_sizes[i] == DICT_SIZES[r]) { map[r] = i; used[i] = true; break; }
            }
        }
    }

    const int*   query   = (const int*)d_in[map[R_query]];
    const int*   support = (const int*)d_in[map[R_support]];
    const int*   qlc     = (const int*)d_in[map[R_qlc]];
    const int*   qrc     = (const int*)d_in[map[R_qrc]];
    const int*   slc     = (const int*)d_in[map[R_slc]];
    const int*   srrc    = (const int*)d_in[map[R_src]];
    const float* emb     = (const float*)d_in[map[R_emb]];
    const float* gcnw    = (const float*)d_in[map[R_gcnw]];
    const float* gcnwb   = (const float*)d_in[map[R_gcnwb]];
    const float* gcnb    = (const float*)d_in[map[R_gcnb]];
    const float* p1w     = (const float*)d_in[map[R_p1w]];
    const float* p1b     = (const float*)d_in[map[R_p1b]];
    const float* p2w     = (const float*)d_in[map[R_p2w]];
    const float* p2b     = (const float*)d_in[map[R_p2b]];
    const float* lng     = (const float*)d_in[map[R_lng]];
    const float* lnb     = (const float*)d_in[map[R_lnb]];
    const float* wih     = (const float*)d_in[map[R_wih]];
    const float* whh     = (const float*)d_in[map[R_whh]];
    const float* bih     = (const float*)d_in[map[R_bih]];
    const float* bhh     = (const float*)d_in[map[R_bhh]];
    float* out = (float*)d_out;

    float *mc, *nb, *H, *O, *enc, *sg, *sgn, *sgr, *biasp, *Gbase, *c, *h1, *h2;
    cudaGetSymbolAddress((void**)&mc,    g_meancat);
    cudaGetSymbolAddress((void**)&nb,    g_nb);
    cudaGetSymbolAddress((void**)&H,     g_H);
    cudaGetSymbolAddress((void**)&O,     g_O);
    cudaGetSymbolAddress((void**)&enc,   g_enc);
    cudaGetSymbolAddress((void**)&sg,    g_sg);
    cudaGetSymbolAddress((void**)&sgn,   g_sgn);
    cudaGetSymbolAddress((void**)&sgr,   g_sgr);
    cudaGetSymbolAddress((void**)&biasp, g_biasp);
    cudaGetSymbolAddress((void**)&Gbase, g_Gbase);
    cudaGetSymbolAddress((void**)&c,     g_c);
    cudaGetSymbolAddress((void**)&h1,    g_h1);
    cudaGetSymbolAddress((void**)&h2,    g_h2);

    unsigned *wihh, *wihl, *whhh, *whhl, *p1h, *p1l, *p2h, *p2l, *gch, *gcl;
    cudaGetSymbolAddress((void**)&wihh, g_wih_h);  cudaGetSymbolAddress((void**)&wihl, g_wih_l);
    cudaGetSymbolAddress((void**)&whhh, g_whh_h);  cudaGetSymbolAddress((void**)&whhl, g_whh_l);
    cudaGetSymbolAddress((void**)&p1h,  g_p1w_h);  cudaGetSymbolAddress((void**)&p1l,  g_p1w_l);
    cudaGetSymbolAddress((void**)&p2h,  g_p2w_h);  cudaGetSymbolAddress((void**)&p2l,  g_p2w_l);
    cudaGetSymbolAddress((void**)&gch,  g_gcnw_h); cudaGetSymbolAddress((void**)&gcl,  g_gcnw_l);

    float* qg   = enc;
    float* senc = enc + (size_t)BQ * DMV;

    // 0) pack weights (bf16x2 hi/lo, k16 fragment order; gates interleaved)
    packw16_kernel<<<dim3(32, 2),  256>>>(gcnw, 512,  0,    gch,  gcl);
    packw16_kernel<<<dim3(32, 8),  256>>>(p1w,  512,  0,    p1h,  p1l);
    packw16_kernel<<<dim3(64, 4),  256>>>(p2w,  1024, 0,    p2h,  p2l);
    packw16_kernel<<<dim3(32, 16), 256>>>(wih,  512,  HID,  wihh, wihl);
    packw16_kernel<<<dim3(32, 16), 256>>>(whh,  1024, HID,  whhh, whhl);

    // 1) neighbor top-K means -> meancat (4106 x 512)
    nbenc_kernel<<<dim3(BQ + FF, 2), 256>>>(query, support, qlc, qrc, slc, srrc, emb, mc);
    // 2) GCN: nb = tanh(mc @ gcnw^T + wb + b)
    tgemm_bf<1,2,0><<<dim3(2, 65), 256>>>(mc, 2*DD, MROWS, gch, gcl, 32,
                                          nb, DD, nullptr, 0, gcnwb, gcnb,
                                          nullptr, nullptr, nullptr);
    // 3) encoder batched over 2053 rows
    tgemm_bf<2,2,0><<<dim3(8, 33), 256>>>(nb, DMV, ER, p1h, p1l, 32,
                                          H, 2*DMV, nullptr, 0, p1b, nullptr,
                                          nullptr, nullptr, nullptr);
    tgemm_bf<0,2,0><<<dim3(4, 33), 256>>>(H, 2*DMV, ER, p2h, p2l, 64,
                                          O, DMV, nb, DMV, p2b, nullptr,
                                          nullptr, nullptr, nullptr);
    ln_kernel<<<ER, 256>>>(O, enc, lng, lnb);
    // 4) support_g mean + normalized copy
    avgnorm_kernel<<<1, 512>>>(sg, sgn, senc);
    // 5) packed sgr + bias (interleaved)
    pack_kernel<<<NG / 8, 256>>>(sgr, biasp, whh, sg, bih, bhh);

    dim3 gg(16, 16);
    // 6) Gbase GEMM + fused LSTM step 1 (c = 0); writes Gbase, c, h1
    tgemm_bf<0,4,1><<<gg, 256>>>(qg, DMV, BQ, wihh, wihl, 32,
                                 Gbase, NG, nullptr, 0, biasp, nullptr,
                                 qg, c, h1);
    // 7) steps 2..4 fused: gates = h_prev @ Whh_sel^T + Gbase + sgr -> LSTM -> h_next
    float* hin = h1; float* hout = h2;
    for (int s = 0; s < 3; s++) {
        tgemm_bf<0,4,2><<<gg, 256>>>(hin, DMV, BQ, whhh, whhl, 32,
                                     nullptr, NG, Gbase, NG, sgr, nullptr,
                                     qg, c, hout);
        float* tmp = hin; hin = hout; hout = tmp;
    }
    // 8) output cosine (hin holds the final h after the last swap)
    final_kernel<<<BQ / 8, 256>>>(out, hin, sgn);
}

// round 16
// speedup vs baseline: 1.2431x; 1.0957x over previous
#include <cuda_runtime.h>
#include <math.h>
#include <stdint.h>

#define VV   200000
#define BQ   2048
#define FF   5
#define NNB  64
#define KSEL 32
#define DD   256
#define DMV  512     // DM
#define HID  1024    // 2*DM
#define NG   2048    // packed gate cols: i,f,g,o each [:512] (block layout)
#define MROWS (2*(BQ+FF))   // 4106 gcn rows
#define ER    (BQ + FF)     // 2053 encoder rows

// ---------------- static scratch ----------------
__device__ float g_meancat[(size_t)4224*2*DD];
__device__ float g_nb[(size_t)4224*DD];
__device__ float g_H[(size_t)2176*2*DMV];
__device__ float g_O[(size_t)2176*DMV];
__device__ float g_enc[(size_t)2176*DMV];
__device__ float g_sg[DMV];
__device__ float g_sgn[DMV];
__device__ float g_sgr[NG];
__device__ float g_biasp[NG];
__device__ float g_Gbase[(size_t)BQ*NG];
__device__ float g_gates[(size_t)BQ*NG];
__device__ float g_c[BQ*DMV];
__device__ float g_h[BQ*DMV];

// packed bf16x2 weights (fragment order, k16 blocks): [pBlock128][kBlock16][1024]
__device__ unsigned g_wih_h[(size_t)16*32*1024],  g_wih_l[(size_t)16*32*1024];
__device__ unsigned g_whh_h[(size_t)16*32*1024],  g_whh_l[(size_t)16*32*1024];
__device__ unsigned g_p1w_h[(size_t)8*32*1024],   g_p1w_l[(size_t)8*32*1024];
__device__ unsigned g_p2w_h[(size_t)4*64*1024],   g_p2w_l[(size_t)4*64*1024];
__device__ unsigned g_gcnw_h[(size_t)2*32*1024],  g_gcnw_l[(size_t)2*32*1024];

// ---------------- helpers ----------------
__device__ __forceinline__ float warp_reduce_sum(float v) {
#pragma unroll
    for (int o = 16; o > 0; o >>= 1) v += __shfl_down_sync(0xffffffffu, v, o);
    return v;
}
__device__ __forceinline__ float sigmoidf_(float x) { return 1.0f / (1.0f + expf(-x)); }
__device__ __forceinline__ int clamp_id(int id) { return (id < 0 || id > VV) ? VV : id; }

__device__ __forceinline__ float block_reduce_256(float v, float* red) {
    int lane = threadIdx.x & 31, w = threadIdx.x >> 5;
    v = warp_reduce_sum(v);
    if (lane == 0) red[w] = v;
    __syncthreads();
    if (threadIdx.x == 0) {
        float s = 0.f;
#pragma unroll
        for (int i = 0; i < 8; i++) s += red[i];
        red[0] = s;
    }
    __syncthreads();
    float s = red[0];
    __syncthreads();
    return s;
}

__device__ __forceinline__ unsigned short f2bf(float x) {
    unsigned short r;
    asm("cvt.rn.bf16.f32 %0, %1;" : "=h"(r) : "f"(x));
    return r;
}
__device__ __forceinline__ float bf2f(unsigned short b) {
    return __uint_as_float((unsigned)b << 16);
}

__device__ __forceinline__ void mma_bf16(float* c, const unsigned* a, const unsigned* b) {
    asm volatile(
        "mma.sync.aligned.m16n8k16.row.col.f32.bf16.bf16.f32 "
        "{%0,%1,%2,%3}, {%4,%5,%6,%7}, {%8,%9}, {%0,%1,%2,%3};"
        : "+f"(c[0]), "+f"(c[1]), "+f"(c[2]), "+f"(c[3])
        : "r"(a[0]), "r"(a[1]), "r"(a[2]), "r"(a[3]), "r"(b[0]), "r"(b[1]));
}

__device__ __forceinline__ void cp16(unsigned* smem, const unsigned* g) {
    unsigned sa = (unsigned)__cvta_generic_to_shared(smem);
    asm volatile("cp.async.cg.shared.global [%0], [%1], 16;" :: "r"(sa), "l"(g));
}
__device__ __forceinline__ void cp_commit() { asm volatile("cp.async.commit_group;"); }
__device__ __forceinline__ void cp_wait0()  { asm volatile("cp.async.wait_group 0;"); }

// ---------------- batched weight pack: bf16x2 k16 fragment order ----------------
// One launch packs all 5 weight matrices. Segment table passed by value.
// gateHid==0: orig row = p*128 + col. gateHid!=0 (block gate layout):
// orig row block = (p>>2)*gateHid + (p&3)*128.
struct PackSeg {
    const float* W;
    unsigned *ph, *pl;
    int ld, gateHid, kBlocks, blockStart;
};
struct PackTable { PackSeg seg[5]; int total; };

__global__ __launch_bounds__(256) void packw16_all_kernel(PackTable tab)
{
    int bid = blockIdx.x;
    // find segment (5 entries, linear scan)
    int si = 0;
#pragma unroll
    for (int i = 1; i < 5; i++) if (bid >= tab.seg[i].blockStart) si = i;
    const PackSeg sgm = tab.seg[si];
    int local = bid - sgm.blockStart;
    int kb = local % sgm.kBlocks;
    int p  = local / sgm.kBlocks;
    int kBlocks = sgm.kBlocks;

    int orig0 = sgm.gateHid ? ((p >> 2) * sgm.gateHid + (p & 3) * 128) : p * 128;
    unsigned* oh = sgm.ph + ((size_t)p * kBlocks + kb) * 1024;
    unsigned* ol = sgm.pl + ((size_t)p * kBlocks + kb) * 1024;
#pragma unroll
    for (int w = threadIdx.x; w < 1024; w += 256) {
        int nblk = w >> 6, rem = w & 63;
        int lane = rem >> 1, reg = rem & 1;
        int col = nblk * 8 + (lane >> 2);
        int k0 = reg * 8 + (lane & 3) * 2;
        const float* wr = sgm.W + (size_t)(orig0 + col) * sgm.ld + kb * 16 + k0;
        float v0 = wr[0], v1 = wr[1];
        unsigned short h0 = f2bf(v0), h1 = f2bf(v1);
        unsigned short l0 = f2bf(v0 - bf2f(h0)), l1 = f2bf(v1 - bf2f(h1));
        oh[w] = (unsigned)h0 | ((unsigned)h1 << 16);
        ol[w] = (unsigned)l0 | ((unsigned)l1 << 16);
    }
}

// ---------------- neighbor encoder: top-K select + mean of (rel,ent) ----------------
__global__ __launch_bounds__(256) void nbenc_kernel(
    const int* __restrict__ query, const int* __restrict__ support,
    const int* __restrict__ qlc, const int* __restrict__ qrc,
    const int* __restrict__ slc, const int* __restrict__ srrc,
    const float* __restrict__ emb, float* __restrict__ meancat_out)
{
    int row = blockIdx.x, side = blockIdx.y;
    const int* conn; int id; int r;
    if (row < BQ) {
        conn = (side == 0 ? qlc : qrc) + row * NNB * 2;
        id   = query[row * 2 + side];
        r    = row * 2 + side;
    } else {
        int f = row - BQ;
        conn = (side == 0 ? slc : srrc) + f * NNB * 2;
        id   = support[f * 2 + side];
        r    = 2 * BQ + f * 2 + side;
    }
    id = clamp_id(id);
    int t = threadIdx.x, lane = t & 31, warp = t >> 5;

    __shared__ __align__(16) float csm[DD];
    __shared__ float sims[NNB];
    __shared__ int   sel[NNB];
    __shared__ float red[8];
    __shared__ float cn_s;

    float cv = emb[(size_t)id * DD + t];
    csm[t] = cv;
    float cs = block_reduce_256(cv * cv, red);
    if (t == 0) cn_s = sqrtf(cs);
    __syncthreads();

    float4 c0 = *(const float4*)&csm[lane * 8];
    float4 c1 = *(const float4*)&csm[lane * 8 + 4];

#pragma unroll
    for (int i = 0; i < 8; i++) {
        int n = warp * 8 + i;
        int eid = clamp_id(conn[n * 2 + 1]);
        const float4* er4 = (const float4*)(emb + (size_t)eid * DD);
        float4 e0 = er4[lane * 2];
        float4 e1 = er4[lane * 2 + 1];
        float dot = e0.x*c0.x + e0.y*c0.y + e0.z*c0.z + e0.w*c0.w
                  + e1.x*c1.x + e1.y*c1.y + e1.z*c1.z + e1.w*c1.w;
        float nn2 = e0.x*e0.x + e0.y*e0.y + e0.z*e0.z + e0.w*e0.w
                  + e1.x*e1.x + e1.y*e1.y + e1.z*e1.z + e1.w*e1.w;
        dot = warp_reduce_sum(dot);
        nn2 = warp_reduce_sum(nn2);
        if (lane == 0) sims[n] = dot / fmaxf(cn_s * sqrtf(nn2), 1e-8f);
    }
    __syncthreads();

    if (t < NNB) {
        float s = sims[t];
        int cnt = 0;
#pragma unroll
        for (int m = 0; m < NNB; m++) {
            float sm = sims[m];
            cnt += (sm > s) || (sm == s && m < t);
        }
        sel[t] = (cnt < KSEL);
    }
    __syncthreads();

    float accR = 0.f, accE = 0.f;
    for (int n = 0; n < NNB; n++) {
        if (!sel[n]) continue;
        int rid = clamp_id(conn[n * 2 + 0]);
        int eid = clamp_id(conn[n * 2 + 1]);
        accR += emb[(size_t)rid * DD + t];
        accE += emb[(size_t)eid * DD + t];
    }
    float* mc = meancat_out + (size_t)r * (2 * DD);
    mc[t]      = accR * (1.0f / KSEL);
    mc[DD + t] = accE * (1.0f / KSEL);
}

// ---------------- unified 3xBF16 GEMM: m16n8k16, 2 smem stages, cp.async B ----------------
// C[M x 128*gx] = epi(A[M x 16*kBlocks] @ Wpacked^T + ...). CTA tile (MI*32) x 128.
// EPI: 0 = acc + v1 + addmat; 1 = tanh(acc+v1+v2); 2 = relu(acc+v1)
template<int EPI, int MI>
__global__ __launch_bounds__(256, 2) void tgemm_bf(
    const float* __restrict__ A, int lda, int Mtot,
    const unsigned* __restrict__ Wh, const unsigned* __restrict__ Wl, int kBlocks,
    float* __restrict__ C, int ldc,
    const float* __restrict__ addmat, int ldm,
    const float* __restrict__ v1, const float* __restrict__ v2)
{
    constexpr int BM = MI * 32;                 // 64 or 128
    __shared__ unsigned Ash[2][BM * 8], Asl[2][BM * 8];
    __shared__ unsigned Bsh[2][1024], Bsl[2][1024];

    const int t = threadIdx.x;
    const int lane = t & 31, warp = t >> 5;
    const int wy = warp >> 2, wx = warp & 3;
    const int m0 = blockIdx.y * BM, n0 = blockIdx.x * 128;

    const unsigned* WH = Wh + (size_t)(n0 >> 7) * kBlocks * 1024;
    const unsigned* WL = Wl + (size_t)(n0 >> 7) * kBlocks * 1024;

    const bool astage = (t < BM * 2);
    const int row = t >> 1;
    const int kin = (t & 1) * 8;
    int ar = m0 + row; if (ar >= Mtot) ar = Mtot - 1;
    const float* Ap = A + (size_t)ar * lda + kin;
    const int baseA = (row >> 4) * 128 + (row & 7) * 16 + (((row & 15) >= 8) ? 1 : 0) + (kin ? 2 : 0);

    float acc[MI][4][4];
#pragma unroll
    for (int i = 0; i < MI; i++)
#pragma unroll
        for (int n = 0; n < 4; n++)
#pragma unroll
            for (int q = 0; q < 4; q++) acc[i][n][q] = 0.f;

    cp16(&Bsh[0][t * 4], WH + t * 4);
    cp16(&Bsl[0][t * 4], WL + t * 4);
    cp_commit();
    float4 va0, va1;
    if (astage) {
        va0 = *(const float4*)Ap;
        va1 = *(const float4*)(Ap + 4);
        float av[8] = {va0.x, va0.y, va0.z, va0.w, va1.x, va1.y, va1.z, va1.w};
#pragma unroll
        for (int j = 0; j < 4; j++) {
            unsigned short h0 = f2bf(av[2*j]),   h1 = f2bf(av[2*j+1]);
            unsigned short l0 = f2bf(av[2*j] - bf2f(h0));
            unsigned short l1 = f2bf(av[2*j+1] - bf2f(h1));
            Ash[0][baseA + j * 4] = (unsigned)h0 | ((unsigned)h1 << 16);
            Asl[0][baseA + j * 4] = (unsigned)l0 | ((unsigned)l1 << 16);
        }
    }
    cp_wait0();
    __syncthreads();

    int s = 0;
    for (int kb = 0; kb < kBlocks; kb++) {
        const bool more = (kb + 1 < kBlocks);
        if (more) {
            const unsigned* bh = WH + (size_t)(kb + 1) * 1024;
            const unsigned* bl = WL + (size_t)(kb + 1) * 1024;
            cp16(&Bsh[s ^ 1][t * 4], bh + t * 4);
            cp16(&Bsl[s ^ 1][t * 4], bl + t * 4);
            cp_commit();
            if (astage) {
                va0 = *(const float4*)(Ap + (kb + 1) * 16);
                va1 = *(const float4*)(Ap + (kb + 1) * 16 + 4);
            }
        }
        uint4 AH[MI], AL[MI];
        uint2 BH[4], BL[4];
#pragma unroll
        for (int i = 0; i < MI; i++) {
            int fi = (wy * MI + i) * 128 + lane * 4;
            AH[i] = *(const uint4*)&Ash[s][fi];
            AL[i] = *(const uint4*)&Asl[s][fi];
        }
#pragma unroll
        for (int n = 0; n < 4; n++) {
            int fn = (wx * 4 + n) * 64 + lane * 2;
            BH[n] = *(const uint2*)&Bsh[s][fn];
            BL[n] = *(const uint2*)&Bsl[s][fn];
        }
#pragma unroll
        for (int i = 0; i < MI; i++)
#pragma unroll
            for (int n = 0; n < 4; n++) {
                mma_bf16(acc[i][n], (const unsigned*)&AH[i], (const unsigned*)&BH[n]);
                mma_bf16(acc[i][n], (const unsigned*)&AL[i], (const unsigned*)&BH[n]);
                mma_bf16(acc[i][n], (const unsigned*)&AH[i], (const unsigned*)&BL[n]);
            }
        if (more) {
            if (astage) {
                float av[8] = {va0.x, va0.y, va0.z, va0.w, va1.x, va1.y, va1.z, va1.w};
#pragma unroll
                for (int j = 0; j < 4; j++) {
                    unsigned short h0 = f2bf(av[2*j]),   h1 = f2bf(av[2*j+1]);
                    unsigned short l0 = f2bf(av[2*j] - bf2f(h0));
                    unsigned short l1 = f2bf(av[2*j+1] - bf2f(h1));
                    Ash[s ^ 1][baseA + j * 4] = (unsigned)h0 | ((unsigned)h1 << 16);
                    Asl[s ^ 1][baseA + j * 4] = (unsigned)l0 | ((unsigned)l1 << 16);
                }
            }
            cp_wait0();
            __syncthreads();
            s ^= 1;
        }
    }

#pragma unroll
    for (int i = 0; i < MI; i++) {
#pragma unroll
        for (int n = 0; n < 4; n++) {
            int col = n0 + wx * 32 + n * 8 + (lane & 3) * 2;
            float v0 = 0.f, v1c = 0.f;
            if (v1) { v0 += v1[col]; v1c += v1[col + 1]; }
            if (EPI == 1 && v2) { v0 += v2[col]; v1c += v2[col + 1]; }
#pragma unroll
            for (int half = 0; half < 2; half++) {
                int m = m0 + wy * MI * 16 + i * 16 + (lane >> 2) + half * 8;
                if (m >= Mtot) continue;
                float x0 = acc[i][n][half * 2 + 0] + v0;
                float x1 = acc[i][n][half * 2 + 1] + v1c;
                float* crow = C + (size_t)m * ldc + col;
                if (EPI == 1) {
                    crow[0] = tanhf(x0); crow[1] = tanhf(x1);
                } else if (EPI == 2) {
                    crow[0] = fmaxf(x0, 0.f); crow[1] = fmaxf(x1, 0.f);
                } else {
                    if (addmat) {
                        const float* mr = addmat + (size_t)m * ldm + col;
                        x0 += mr[0]; x1 += mr[1];
                    }
                    crow[0] = x0; crow[1] = x1;
                }
            }
        }
    }
}

// ---------------- LayerNorm over 512 per row ----------------
__global__ __launch_bounds__(256) void ln_kernel(
    const float* __restrict__ O, float* __restrict__ Y,
    const float* __restrict__ lng, const float* __restrict__ lnb)
{
    int row = blockIdx.x, t = threadIdx.x;
    __shared__ float red[8];
    float o0 = O[(size_t)row * DMV + t];
    float o1 = O[(size_t)row * DMV + t + 256];
    float msum = block_reduce_256(o0 + o1, red);
    float m = msum * (1.0f / DMV);
    float d0 = o0 - m, d1 = o1 - m;
    float vsum = block_reduce_256(d0 * d0 + d1 * d1, red);
    float rstd = rsqrtf(vsum * (1.0f / DMV) + 1e-5f);
    Y[(size_t)row * DMV + t]       = d0 * rstd * lng[t]       + lnb[t];
    Y[(size_t)row * DMV + t + 256] = d1 * rstd * lng[t + 256] + lnb[t + 256];
}

// ---------------- mean over F support rows + normalized copy ----------------
__global__ void avgnorm_kernel(float* __restrict__ sg, float* __restrict__ sgn,
                               const float* __restrict__ senc)
{
    int t = threadIdx.x; // 512 threads
    __shared__ float red[16];
    float s = 0.f;
#pragma unroll
    for (int f = 0; f < FF; f++) s += senc[f * DMV + t];
    s *= (1.0f / FF);
    sg[t] = s;
    int lane = t & 31, w = t >> 5;
    float v = warp_reduce_sum(s * s);
    if (lane == 0) red[w] = v;
    __syncthreads();
    if (t == 0) {
        float tot = 0.f;
#pragma unroll
        for (int i = 0; i < 16; i++) tot += red[i];
        red[0] = sqrtf(tot);
    }
    __syncthreads();
    float nrm = red[0];
    sgn[t] = s / fmaxf(nrm, 1e-12f);
}

// ---------------- packed constants: sgr[n], biasp[n] (block: n>>9 = gate) ----------------
__global__ __launch_bounds__(256) void pack_kernel(
    float* __restrict__ sgr, float* __restrict__ biasp,
    const float* __restrict__ whh, const float* __restrict__ sg,
    const float* __restrict__ bih, const float* __restrict__ bhh)
{
    int n = (blockIdx.x * blockDim.x + threadIdx.x) >> 5;
    int lane = threadIdx.x & 31;
    if (n >= NG) return;
    int jf = (n >> 9) * HID + (n & 511);
    const float* wr = whh + (size_t)jf * HID + DMV;
    float a = 0.f;
#pragma unroll
    for (int k = lane; k < DMV; k += 32) a += wr[k] * sg[k];
    a = warp_reduce_sum(a);
    if (lane == 0) {
        sgr[n] = a;
        biasp[n] = bih[jf] + bhh[jf];
    }
}

// ---------------- LSTM elementwise step ----------------
__global__ __launch_bounds__(256) void lstm_step_kernel(
    const float* __restrict__ G, const float* __restrict__ qg,
    float* __restrict__ c, float* __restrict__ h, int first)
{
    int idx = blockIdx.x * blockDim.x + threadIdx.x;
    int b = idx >> 9, j = idx & 511;
    const float* g = G + (size_t)b * NG;
    float gi = g[j], gf = g[512 + j], gg = g[1024 + j], go = g[1536 + j];
    float cn = sigmoidf_(gi) * tanhf(gg);
    if (!first) cn += sigmoidf_(gf) * c[idx];
    c[idx] = cn;
    h[idx] = qg[idx] + sigmoidf_(go) * tanhf(cn);
}

// ---------------- final cosine output ----------------
__global__ __launch_bounds__(256) void final_kernel(
    float* __restrict__ out, const float* __restrict__ h,
    const float* __restrict__ sgn)
{
    int b = (blockIdx.x * blockDim.x + threadIdx.x) >> 5;
    int lane = threadIdx.x & 31;
    if (b >= BQ) return;
    float nn = 0.f, dd = 0.f;
#pragma unroll
    for (int d = lane; d < DMV; d += 32) {
        float hv = h[(size_t)b * DMV + d];
        nn += hv * hv;
        dd += hv * sgn[d];
    }
    nn = warp_reduce_sum(nn);
    dd = warp_reduce_sum(dd);
    if (lane == 0) out[b] = dd / fmaxf(sqrtf(nn), 1e-12f);
}

// ---------------- input binding ----------------
enum {
    R_query=0, R_support, R_qlc, R_qld, R_qrc, R_qrd, R_slc, R_sld, R_src, R_srd,
    R_emb, R_gcnw, R_gcnwb, R_gcnb, R_p1w, R_p1b, R_p2w, R_p2b, R_lng, R_lnb,
    R_wih, R_whh, R_bih, R_bhh, R_COUNT
};
static const int DICT_SIZES[R_COUNT] = {
    4096, 10, 262144, 2048, 262144, 2048, 640, 5, 640, 5,
    51200256, 131072, 256, 256, 524288, 1024, 524288, 512, 512, 512,
    2097152, 4194304, 4096, 4096
};
static bool sizes_match(const int* s, const int* exp, int n) {
    for (int i = 0; i < n; i++) if (s[i] != exp[i]) return false;
    return true;
}

// ---------------- launcher ----------------
extern "C" void kernel_launch(void* const* d_in, const int* in_sizes, int n_in,
                              void* d_out, int out_size)
{
    int map[R_COUNT];
    if (n_in >= R_COUNT && sizes_match(in_sizes, DICT_SIZES, R_COUNT)) {
        for (int r = 0; r < R_COUNT; r++) map[r] = r;
    } else {
        bool used[64] = {false};
        for (int r = 0; r < R_COUNT; r++) {
            map[r] = 0;
            for (int i = 0; i < n_in && i < 64; i++) {
                if (!used[i] && in_sizes[i] == DICT_SIZES[r]) { map[r] = i; used[i] = true; break; }
            }
        }
    }

    const int*   query   = (const int*)d_in[map[R_query]];
    const int*   support = (const int*)d_in[map[R_support]];
    const int*   qlc     = (const int*)d_in[map[R_qlc]];
    const int*   qrc     = (const int*)d_in[map[R_qrc]];
    const int*   slc     = (const int*)d_in[map[R_slc]];
    const int*   srrc    = (const int*)d_in[map[R_src]];
    const float* emb     = (const float*)d_in[map[R_emb]];
    const float* gcnw    = (const float*)d_in[map[R_gcnw]];
    const float* gcnwb   = (const float*)d_in[map[R_gcnwb]];
    const float* gcnb    = (const float*)d_in[map[R_gcnb]];
    const float* p1w     = (const float*)d_in[map[R_p1w]];
    const float* p1b     = (const float*)d_in[map[R_p1b]];
    const float* p2w     = (const float*)d_in[map[R_p2w]];
    const float* p2b     = (const float*)d_in[map[R_p2b]];
    const float* lng     = (const float*)d_in[map[R_lng]];
    const float* lnb     = (const float*)d_in[map[R_lnb]];
    const float* wih     = (const float*)d_in[map[R_wih]];
    const float* whh     = (const float*)d_in[map[R_whh]];
    const float* bih     = (const float*)d_in[map[R_bih]];
    const float* bhh     = (const float*)d_in[map[R_bhh]];
    float* out = (float*)d_out;

    float *mc, *nb, *H, *O, *enc, *sg, *sgn, *sgr, *biasp, *Gbase, *gates, *c, *h;
    cudaGetSymbolAddress((void**)&mc,    g_meancat);
    cudaGetSymbolAddress((void**)&nb,    g_nb);
    cudaGetSymbolAddress((void**)&H,     g_H);
    cudaGetSymbolAddress((void**)&O,     g_O);
    cudaGetSymbolAddress((void**)&enc,   g_enc);
    cudaGetSymbolAddress((void**)&sg,    g_sg);
    cudaGetSymbolAddress((void**)&sgn,   g_sgn);
    cudaGetSymbolAddress((void**)&sgr,   g_sgr);
    cudaGetSymbolAddress((void**)&biasp, g_biasp);
    cudaGetSymbolAddress((void**)&Gbase, g_Gbase);
    cudaGetSymbolAddress((void**)&gates, g_gates);
    cudaGetSymbolAddress((void**)&c,     g_c);
    cudaGetSymbolAddress((void**)&h,     g_h);

    unsigned *wihh, *wihl, *whhh, *whhl, *p1h, *p1l, *p2h, *p2l, *gch, *gcl;
    cudaGetSymbolAddress((void**)&wihh, g_wih_h);  cudaGetSymbolAddress((void**)&wihl, g_wih_l);
    cudaGetSymbolAddress((void**)&whhh, g_whh_h);  cudaGetSymbolAddress((void**)&whhl, g_whh_l);
    cudaGetSymbolAddress((void**)&p1h,  g_p1w_h);  cudaGetSymbolAddress((void**)&p1l,  g_p1w_l);
    cudaGetSymbolAddress((void**)&p2h,  g_p2w_h);  cudaGetSymbolAddress((void**)&p2l,  g_p2w_l);
    cudaGetSymbolAddress((void**)&gch,  g_gcnw_h); cudaGetSymbolAddress((void**)&gcl,  g_gcnw_l);

    float* qg   = enc;
    float* senc = enc + (size_t)BQ * DMV;

    // 0) pack all weights in ONE launch (bf16x2 hi/lo, k16 fragment order)
    PackTable tab;
    // seg: {W, ph, pl, ld, gateHid, kBlocks, blockStart}
    tab.seg[0] = { gcnw, gch,  gcl,  512,  0,   32, 0 };                 // 32*2  = 64
    tab.seg[1] = { p1w,  p1h,  p1l,  512,  0,   32, 64 };                // 32*8  = 256
    tab.seg[2] = { p2w,  p2h,  p2l,  1024, 0,   64, 64 + 256 };          // 64*4  = 256
    tab.seg[3] = { wih,  wihh, wihl, 512,  HID, 32, 64 + 256 + 256 };    // 32*16 = 512
    tab.seg[4] = { whh,  whhh, whhl, 1024, HID, 32, 64 + 256 + 256 + 512 }; // 512
    tab.total = 64 + 256 + 256 + 512 + 512;   // 1600
    packw16_all_kernel<<<tab.total, 256>>>(tab);

    // 1) neighbor top-K means -> meancat (4106 x 512)
    nbenc_kernel<<<dim3(BQ + FF, 2), 256>>>(query, support, qlc, qrc, slc, srrc, emb, mc);
    // 2) GCN: nb = tanh(mc @ gcnw^T + wb + b)
    tgemm_bf<1,2><<<dim3(2, 65), 256>>>(mc, 2*DD, MROWS, gch, gcl, 32,
                                        nb, DD, nullptr, 0, gcnwb, gcnb);
    // 3) encoder batched over 2053 rows
    tgemm_bf<2,2><<<dim3(8, 33), 256>>>(nb, DMV, ER, p1h, p1l, 32,
                                        H, 2*DMV, nullptr, 0, p1b, nullptr);
    tgemm_bf<0,2><<<dim3(4, 33), 256>>>(H, 2*DMV, ER, p2h, p2l, 64,
                                        O, DMV, nb, DMV, p2b, nullptr);
    ln_kernel<<<ER, 256>>>(O, enc, lng, lnb);
    // 4) support_g mean + normalized copy
    avgnorm_kernel<<<1, 512>>>(sg, sgn, senc);
    // 5) packed sgr + bias
    pack_kernel<<<NG / 8, 256>>>(sgr, biasp, whh, sg, bih, bhh);

    dim3 gg(16, 16);
    // 6) Gbase = qg @ Wih_sel^T + (bih+bhh)_packed
    tgemm_bf<0,4><<<gg, 256>>>(qg, DMV, BQ, wihh, wihl, 32,
                               Gbase, NG, nullptr, 0, biasp, nullptr);
    // 7) step 1 (c = 0)
    lstm_step_kernel<<<(BQ * DMV) / 256, 256>>>(Gbase, qg, c, h, 1);
    // 8) steps 2..4: gates = h @ Whh_sel[:, :512]^T + Gbase + sgr
    for (int s = 0; s < 3; s++) {
        tgemm_bf<0,4><<<gg, 256>>>(h, DMV, BQ, whhh, whhl, 32,
                                   gates, NG, Gbase, NG, sgr, nullptr);
        lstm_step_kernel<<<(BQ * DMV) / 256, 256>>>(gates, qg, c, h, 0);
    }
    // 9) output cosine
    final_kernel<<<BQ / 8, 256>>>(out, h, sgn);
}

// round 17
// speedup vs baseline: 1.2597x; 1.0133x over previous
#include <cuda_runtime.h>
#include <math.h>
#include <stdint.h>

#define VV   200000
#define BQ   2048
#define FF   5
#define NNB  64
#define KSEL 32
#define DD   256
#define DMV  512     // DM
#define HID  1024    // 2*DM
#define NG   2048    // packed gate cols: i,f,g,o each [:512] (block layout)
#define MROWS (2*(BQ+FF))   // 4106 gcn rows
#define ER    (BQ + FF)     // 2053 encoder rows

// ---------------- static scratch ----------------
__device__ float g_meancat[(size_t)4224*2*DD];
__device__ float g_nb[(size_t)4224*DD];
__device__ float g_H[(size_t)2176*2*DMV];
__device__ float g_O[(size_t)2176*DMV];
__device__ float g_enc[(size_t)2176*DMV];
__device__ float g_sg[DMV];
__device__ float g_sgn[DMV];
__device__ float g_sgr[NG];
__device__ float g_biasp[NG];
__device__ float g_Gbase[(size_t)BQ*NG];
__device__ float g_gates[(size_t)BQ*NG];
__device__ float g_c[BQ*DMV];
__device__ float g_h[BQ*DMV];

// packed bf16x2 weights (fragment order, k16 blocks): [pBlock128][kBlock16][1024]
__device__ unsigned g_wih_h[(size_t)16*32*1024],  g_wih_l[(size_t)16*32*1024];
__device__ unsigned g_whh_h[(size_t)16*32*1024],  g_whh_l[(size_t)16*32*1024];
__device__ unsigned g_p1w_h[(size_t)8*32*1024],   g_p1w_l[(size_t)8*32*1024];
__device__ unsigned g_p2w_h[(size_t)4*64*1024],   g_p2w_l[(size_t)4*64*1024];
__device__ unsigned g_gcnw_h[(size_t)2*32*1024],  g_gcnw_l[(size_t)2*32*1024];

// ---------------- helpers ----------------
__device__ __forceinline__ float warp_reduce_sum(float v) {
#pragma unroll
    for (int o = 16; o > 0; o >>= 1) v += __shfl_down_sync(0xffffffffu, v, o);
    return v;
}
__device__ __forceinline__ float sigmoidf_(float x) { return 1.0f / (1.0f + expf(-x)); }
__device__ __forceinline__ int clamp_id(int id) { return (id < 0 || id > VV) ? VV : id; }

__device__ __forceinline__ float block_reduce_256(float v, float* red) {
    int lane = threadIdx.x & 31, w = threadIdx.x >> 5;
    v = warp_reduce_sum(v);
    if (lane == 0) red[w] = v;
    __syncthreads();
    if (threadIdx.x == 0) {
        float s = 0.f;
#pragma unroll
        for (int i = 0; i < 8; i++) s += red[i];
        red[0] = s;
    }
    __syncthreads();
    float s = red[0];
    __syncthreads();
    return s;
}

__device__ __forceinline__ unsigned short f2bf(float x) {
    unsigned short r;
    asm("cvt.rn.bf16.f32 %0, %1;" : "=h"(r) : "f"(x));
    return r;
}
__device__ __forceinline__ float bf2f(unsigned short b) {
    return __uint_as_float((unsigned)b << 16);
}

__device__ __forceinline__ void mma_bf16(float* c, const unsigned* a, const unsigned* b) {
    asm volatile(
        "mma.sync.aligned.m16n8k16.row.col.f32.bf16.bf16.f32 "
        "{%0,%1,%2,%3}, {%4,%5,%6,%7}, {%8,%9}, {%0,%1,%2,%3};"
        : "+f"(c[0]), "+f"(c[1]), "+f"(c[2]), "+f"(c[3])
        : "r"(a[0]), "r"(a[1]), "r"(a[2]), "r"(a[3]), "r"(b[0]), "r"(b[1]));
}

__device__ __forceinline__ void cp16(unsigned* smem, const unsigned* g) {
    unsigned sa = (unsigned)__cvta_generic_to_shared(smem);
    asm volatile("cp.async.cg.shared.global [%0], [%1], 16;" :: "r"(sa), "l"(g));
}
__device__ __forceinline__ void cp_commit() { asm volatile("cp.async.commit_group;"); }
__device__ __forceinline__ void cp_wait0()  { asm volatile("cp.async.wait_group 0;"); }

// ---------------- batched weight pack: bf16x2 k16 fragment order ----------------
struct PackSeg {
    const float* W;
    unsigned *ph, *pl;
    int ld, gateHid, kBlocks, blockStart;
};
struct PackTable { PackSeg seg[5]; int total; };

__global__ __launch_bounds__(256) void packw16_all_kernel(PackTable tab)
{
    int bid = blockIdx.x;
    int si = 0;
#pragma unroll
    for (int i = 1; i < 5; i++) if (bid >= tab.seg[i].blockStart) si = i;
    const PackSeg sgm = tab.seg[si];
    int local = bid - sgm.blockStart;
    int kb = local % sgm.kBlocks;
    int p  = local / sgm.kBlocks;
    int kBlocks = sgm.kBlocks;

    int orig0 = sgm.gateHid ? ((p >> 2) * sgm.gateHid + (p & 3) * 128) : p * 128;
    unsigned* oh = sgm.ph + ((size_t)p * kBlocks + kb) * 1024;
    unsigned* ol = sgm.pl + ((size_t)p * kBlocks + kb) * 1024;
#pragma unroll
    for (int w = threadIdx.x; w < 1024; w += 256) {
        int nblk = w >> 6, rem = w & 63;
        int lane = rem >> 1, reg = rem & 1;
        int col = nblk * 8 + (lane >> 2);
        int k0 = reg * 8 + (lane & 3) * 2;
        const float* wr = sgm.W + (size_t)(orig0 + col) * sgm.ld + kb * 16 + k0;
        float v0 = wr[0], v1 = wr[1];
        unsigned short h0 = f2bf(v0), h1 = f2bf(v1);
        unsigned short l0 = f2bf(v0 - bf2f(h0)), l1 = f2bf(v1 - bf2f(h1));
        oh[w] = (unsigned)h0 | ((unsigned)h1 << 16);
        ol[w] = (unsigned)l0 | ((unsigned)l1 << 16);
    }
}

// ---------------- neighbor encoder: top-K select + mean of (rel,ent) ----------------
// mean pass uses compacted index list (ascending n) + 4x unrolled gathers (MLP 8)
__global__ __launch_bounds__(256) void nbenc_kernel(
    const int* __restrict__ query, const int* __restrict__ support,
    const int* __restrict__ qlc, const int* __restrict__ qrc,
    const int* __restrict__ slc, const int* __restrict__ srrc,
    const float* __restrict__ emb, float* __restrict__ meancat_out)
{
    int row = blockIdx.x, side = blockIdx.y;
    const int* conn; int id; int r;
    if (row < BQ) {
        conn = (side == 0 ? qlc : qrc) + row * NNB * 2;
        id   = query[row * 2 + side];
        r    = row * 2 + side;
    } else {
        int f = row - BQ;
        conn = (side == 0 ? slc : srrc) + f * NNB * 2;
        id   = support[f * 2 + side];
        r    = 2 * BQ + f * 2 + side;
    }
    id = clamp_id(id);
    int t = threadIdx.x, lane = t & 31, warp = t >> 5;

    __shared__ __align__(16) float csm[DD];
    __shared__ float sims[NNB];
    __shared__ int   sel[NNB];
    __shared__ int   sidx[KSEL];
    __shared__ float red[8];
    __shared__ float cn_s;

    float cv = emb[(size_t)id * DD + t];
    csm[t] = cv;
    float cs = block_reduce_256(cv * cv, red);
    if (t == 0) cn_s = sqrtf(cs);
    __syncthreads();

    float4 c0 = *(const float4*)&csm[lane * 8];
    float4 c1 = *(const float4*)&csm[lane * 8 + 4];

#pragma unroll
    for (int i = 0; i < 8; i++) {
        int n = warp * 8 + i;
        int eid = clamp_id(conn[n * 2 + 1]);
        const float4* er4 = (const float4*)(emb + (size_t)eid * DD);
        float4 e0 = er4[lane * 2];
        float4 e1 = er4[lane * 2 + 1];
        float dot = e0.x*c0.x + e0.y*c0.y + e0.z*c0.z + e0.w*c0.w
                  + e1.x*c1.x + e1.y*c1.y + e1.z*c1.z + e1.w*c1.w;
        float nn2 = e0.x*e0.x + e0.y*e0.y + e0.z*e0.z + e0.w*e0.w
                  + e1.x*e1.x + e1.y*e1.y + e1.z*e1.z + e1.w*e1.w;
        dot = warp_reduce_sum(dot);
        nn2 = warp_reduce_sum(nn2);
        if (lane == 0) sims[n] = dot / fmaxf(cn_s * sqrtf(nn2), 1e-8f);
    }
    __syncthreads();

    // stable top-K membership (ties -> lower index)
    if (t < NNB) {
        float s = sims[t];
        int cnt = 0;
#pragma unroll
        for (int m = 0; m < NNB; m++) {
            float sm = sims[m];
            cnt += (sm > s) || (sm == s && m < t);
        }
        sel[t] = (cnt < KSEL);
    }
    __syncthreads();
    // compact selected indices in ascending-n order (exactly KSEL selected)
    if (t < NNB && sel[t]) {
        int pos = 0;
        for (int m = 0; m < t; m++) pos += sel[m];
        sidx[pos] = t;
    }
    __syncthreads();

    // mean pass: 4x unrolled gathers, adds in ascending-n order (fp-identical)
    float accR = 0.f, accE = 0.f;
#pragma unroll
    for (int k = 0; k < KSEL; k += 4) {
        int n0 = sidx[k], n1 = sidx[k+1], n2 = sidx[k+2], n3 = sidx[k+3];
        int r0 = clamp_id(conn[n0*2]), e0 = clamp_id(conn[n0*2+1]);
        int r1 = clamp_id(conn[n1*2]), e1 = clamp_id(conn[n1*2+1]);
        int r2 = clamp_id(conn[n2*2]), e2 = clamp_id(conn[n2*2+1]);
        int r3 = clamp_id(conn[n3*2]), e3 = clamp_id(conn[n3*2+1]);
        float rv0 = emb[(size_t)r0*DD + t], ev0 = emb[(size_t)e0*DD + t];
        float rv1 = emb[(size_t)r1*DD + t], ev1 = emb[(size_t)e1*DD + t];
        float rv2 = emb[(size_t)r2*DD + t], ev2 = emb[(size_t)e2*DD + t];
        float rv3 = emb[(size_t)r3*DD + t], ev3 = emb[(size_t)e3*DD + t];
        accR += rv0; accR += rv1; accR += rv2; accR += rv3;
        accE += ev0; accE += ev1; accE += ev2; accE += ev3;
    }
    float* mc = meancat_out + (size_t)r * (2 * DD);
    mc[t]      = accR * (1.0f / KSEL);
    mc[DD + t] = accE * (1.0f / KSEL);
}

// ---------------- unified 3xBF16 GEMM: m16n8k16, 2 smem stages, cp.async B ----------------
// EPI: 0 = acc + v1 + addmat; 1 = tanh(acc+v1+v2); 2 = relu(acc+v1)
template<int EPI, int MI>
__global__ __launch_bounds__(256, 2) void tgemm_bf(
    const float* __restrict__ A, int lda, int Mtot,
    const unsigned* __restrict__ Wh, const unsigned* __restrict__ Wl, int kBlocks,
    float* __restrict__ C, int ldc,
    const float* __restrict__ addmat, int ldm,
    const float* __restrict__ v1, const float* __restrict__ v2)
{
    constexpr int BM = MI * 32;                 // 64 or 128
    __shared__ unsigned Ash[2][BM * 8], Asl[2][BM * 8];
    __shared__ unsigned Bsh[2][1024], Bsl[2][1024];

    const int t = threadIdx.x;
    const int lane = t & 31, warp = t >> 5;
    const int wy = warp >> 2, wx = warp & 3;
    const int m0 = blockIdx.y * BM, n0 = blockIdx.x * 128;

    const unsigned* WH = Wh + (size_t)(n0 >> 7) * kBlocks * 1024;
    const unsigned* WL = Wl + (size_t)(n0 >> 7) * kBlocks * 1024;

    const bool astage = (t < BM * 2);
    const int row = t >> 1;
    const int kin = (t & 1) * 8;
    int ar = m0 + row; if (ar >= Mtot) ar = Mtot - 1;
    const float* Ap = A + (size_t)ar * lda + kin;
    const int baseA = (row >> 4) * 128 + (row & 7) * 16 + (((row & 15) >= 8) ? 1 : 0) + (kin ? 2 : 0);

    float acc[MI][4][4];
#pragma unroll
    for (int i = 0; i < MI; i++)
#pragma unroll
        for (int n = 0; n < 4; n++)
#pragma unroll
            for (int q = 0; q < 4; q++) acc[i][n][q] = 0.f;

    cp16(&Bsh[0][t * 4], WH + t * 4);
    cp16(&Bsl[0][t * 4], WL + t * 4);
    cp_commit();
    float4 va0, va1;
    if (astage) {
        va0 = *(const float4*)Ap;
        va1 = *(const float4*)(Ap + 4);
        float av[8] = {va0.x, va0.y, va0.z, va0.w, va1.x, va1.y, va1.z, va1.w};
#pragma unroll
        for (int j = 0; j < 4; j++) {
            unsigned short h0 = f2bf(av[2*j]),   h1 = f2bf(av[2*j+1]);
            unsigned short l0 = f2bf(av[2*j] - bf2f(h0));
            unsigned short l1 = f2bf(av[2*j+1] - bf2f(h1));
            Ash[0][baseA + j * 4] = (unsigned)h0 | ((unsigned)h1 << 16);
            Asl[0][baseA + j * 4] = (unsigned)l0 | ((unsigned)l1 << 16);
        }
    }
    cp_wait0();
    __syncthreads();

    int s = 0;
    for (int kb = 0; kb < kBlocks; kb++) {
        const bool more = (kb + 1 < kBlocks);
        if (more) {
            const unsigned* bh = WH + (size_t)(kb + 1) * 1024;
            const unsigned* bl = WL + (size_t)(kb + 1) * 1024;
            cp16(&Bsh[s ^ 1][t * 4], bh + t * 4);
            cp16(&Bsl[s ^ 1][t * 4], bl + t * 4);
            cp_commit();
            if (astage) {
                va0 = *(const float4*)(Ap + (kb + 1) * 16);
                va1 = *(const float4*)(Ap + (kb + 1) * 16 + 4);
            }
        }
        uint4 AH[MI], AL[MI];
        uint2 BH[4], BL[4];
#pragma unroll
        for (int i = 0; i < MI; i++) {
            int fi = (wy * MI + i) * 128 + lane * 4;
            AH[i] = *(const uint4*)&Ash[s][fi];
            AL[i] = *(const uint4*)&Asl[s][fi];
        }
#pragma unroll
        for (int n = 0; n < 4; n++) {
            int fn = (wx * 4 + n) * 64 + lane * 2;
            BH[n] = *(const uint2*)&Bsh[s][fn];
            BL[n] = *(const uint2*)&Bsl[s][fn];
        }
#pragma unroll
        for (int i = 0; i < MI; i++)
#pragma unroll
            for (int n = 0; n < 4; n++) {
                mma_bf16(acc[i][n], (const unsigned*)&AH[i], (const unsigned*)&BH[n]);
                mma_bf16(acc[i][n], (const unsigned*)&AL[i], (const unsigned*)&BH[n]);
                mma_bf16(acc[i][n], (const unsigned*)&AH[i], (const unsigned*)&BL[n]);
            }
        if (more) {
            if (astage) {
                float av[8] = {va0.x, va0.y, va0.z, va0.w, va1.x, va1.y, va1.z, va1.w};
#pragma unroll
                for (int j = 0; j < 4; j++) {
                    unsigned short h0 = f2bf(av[2*j]),   h1 = f2bf(av[2*j+1]);
                    unsigned short l0 = f2bf(av[2*j] - bf2f(h0));
                    unsigned short l1 = f2bf(av[2*j+1] - bf2f(h1));
                    Ash[s ^ 1][baseA + j * 4] = (unsigned)h0 | ((unsigned)h1 << 16);
                    Asl[s ^ 1][baseA + j * 4] = (unsigned)l0 | ((unsigned)l1 << 16);
                }
            }
            cp_wait0();
            __syncthreads();
            s ^= 1;
        }
    }

#pragma unroll
    for (int i = 0; i < MI; i++) {
#pragma unroll
        for (int n = 0; n < 4; n++) {
            int col = n0 + wx * 32 + n * 8 + (lane & 3) * 2;
            float v0 = 0.f, v1c = 0.f;
            if (v1) { v0 += v1[col]; v1c += v1[col + 1]; }
            if (EPI == 1 && v2) { v0 += v2[col]; v1c += v2[col + 1]; }
#pragma unroll
            for (int half = 0; half < 2; half++) {
                int m = m0 + wy * MI * 16 + i * 16 + (lane >> 2) + half * 8;
                if (m >= Mtot) continue;
                float x0 = acc[i][n][half * 2 + 0] + v0;
                float x1 = acc[i][n][half * 2 + 1] + v1c;
                float* crow = C + (size_t)m * ldc + col;
                if (EPI == 1) {
                    crow[0] = tanhf(x0); crow[1] = tanhf(x1);
                } else if (EPI == 2) {
                    crow[0] = fmaxf(x0, 0.f); crow[1] = fmaxf(x1, 0.f);
                } else {
                    if (addmat) {
                        const float* mr = addmat + (size_t)m * ldm + col;
                        x0 += mr[0]; x1 += mr[1];
                    }
                    crow[0] = x0; crow[1] = x1;
                }
            }
        }
    }
}

// ---------------- LayerNorm over 512 per row ----------------
__global__ __launch_bounds__(256) void ln_kernel(
    const float* __restrict__ O, float* __restrict__ Y,
    const float* __restrict__ lng, const float* __restrict__ lnb)
{
    int row = blockIdx.x, t = threadIdx.x;
    __shared__ float red[8];
    float o0 = O[(size_t)row * DMV + t];
    float o1 = O[(size_t)row * DMV + t + 256];
    float msum = block_reduce_256(o0 + o1, red);
    float m = msum * (1.0f / DMV);
    float d0 = o0 - m, d1 = o1 - m;
    float vsum = block_reduce_256(d0 * d0 + d1 * d1, red);
    float rstd = rsqrtf(vsum * (1.0f / DMV) + 1e-5f);
    Y[(size_t)row * DMV + t]       = d0 * rstd * lng[t]       + lnb[t];
    Y[(size_t)row * DMV + t + 256] = d1 * rstd * lng[t + 256] + lnb[t + 256];
}

// ---------------- mean over F support rows + normalized copy ----------------
__global__ void avgnorm_kernel(float* __restrict__ sg, float* __restrict__ sgn,
                               const float* __restrict__ senc)
{
    int t = threadIdx.x; // 512 threads
    __shared__ float red[16];
    float s = 0.f;
#pragma unroll
    for (int f = 0; f < FF; f++) s += senc[f * DMV + t];
    s *= (1.0f / FF);
    sg[t] = s;
    int lane = t & 31, w = t >> 5;
    float v = warp_reduce_sum(s * s);
    if (lane == 0) red[w] = v;
    __syncthreads();
    if (t == 0) {
        float tot = 0.f;
#pragma unroll
        for (int i = 0; i < 16; i++) tot += red[i];
        red[0] = sqrtf(tot);
    }
    __syncthreads();
    float nrm = red[0];
    sgn[t] = s / fmaxf(nrm, 1e-12f);
}

// ---------------- packed constants: sgr[n], biasp[n] (block: n>>9 = gate) ----------------
__global__ __launch_bounds__(256) void pack_kernel(
    float* __restrict__ sgr, float* __restrict__ biasp,
    const float* __restrict__ whh, const float* __restrict__ sg,
    const float* __restrict__ bih, const float* __restrict__ bhh)
{
    int n = (blockIdx.x * blockDim.x + threadIdx.x) >> 5;
    int lane = threadIdx.x & 31;
    if (n >= NG) return;
    int jf = (n >> 9) * HID + (n & 511);
    const float* wr = whh + (size_t)jf * HID + DMV;
    float a = 0.f;
#pragma unroll
    for (int k = lane; k < DMV; k += 32) a += wr[k] * sg[k];
    a = warp_reduce_sum(a);
    if (lane == 0) {
        sgr[n] = a;
        biasp[n] = bih[jf] + bhh[jf];
    }
}

// ---------------- LSTM elementwise step ----------------
__global__ __launch_bounds__(256) void lstm_step_kernel(
    const float* __restrict__ G, const float* __restrict__ qg,
    float* __restrict__ c, float* __restrict__ h, int first)
{
    int idx = blockIdx.x * blockDim.x + threadIdx.x;
    int b = idx >> 9, j = idx & 511;
    const float* g = G + (size_t)b * NG;
    float gi = g[j], gf = g[512 + j], gg = g[1024 + j], go = g[1536 + j];
    float cn = sigmoidf_(gi) * tanhf(gg);
    if (!first) cn += sigmoidf_(gf) * c[idx];
    c[idx] = cn;
    h[idx] = qg[idx] + sigmoidf_(go) * tanhf(cn);
}

// ---------------- final cosine output ----------------
__global__ __launch_bounds__(256) void final_kernel(
    float* __restrict__ out, const float* __restrict__ h,
    const float* __restrict__ sgn)
{
    int b = (blockIdx.x * blockDim.x + threadIdx.x) >> 5;
    int lane = threadIdx.x & 31;
    if (b >= BQ) return;
    float nn = 0.f, dd = 0.f;
#pragma unroll
    for (int d = lane; d < DMV; d += 32) {
        float hv = h[(size_t)b * DMV + d];
        nn += hv * hv;
        dd += hv * sgn[d];
    }
    nn = warp_reduce_sum(nn);
    dd = warp_reduce_sum(dd);
    if (lane == 0) out[b] = dd / fmaxf(sqrtf(nn), 1e-12f);
}

// ---------------- input binding ----------------
enum {
    R_query=0, R_support, R_qlc, R_qld, R_qrc, R_qrd, R_slc, R_sld, R_src, R_srd,
    R_emb, R_gcnw, R_gcnwb, R_gcnb, R_p1w, R_p1b, R_p2w, R_p2b, R_lng, R_lnb,
    R_wih, R_whh, R_bih, R_bhh, R_COUNT
};
static const int DICT_SIZES[R_COUNT] = {
    4096, 10, 262144, 2048, 262144, 2048, 640, 5, 640, 5,
    51200256, 131072, 256, 256, 524288, 1024, 524288, 512, 512, 512,
    2097152, 4194304, 4096, 4096
};
static bool sizes_match(const int* s, const int* exp, int n) {
    for (int i = 0; i < n; i++) if (s[i] != exp[i]) return false;
    return true;
}

// ---------------- launcher ----------------
extern "C" void kernel_launch(void* const* d_in, const int* in_sizes, int n_in,
                              void* d_out, int out_size)
{
    int map[R_COUNT];
    if (n_in >= R_COUNT && sizes_match(in_sizes, DICT_SIZES, R_COUNT)) {
        for (int r = 0; r < R_COUNT; r++) map[r] = r;
    } else {
        bool used[64] = {false};
        for (int r = 0; r < R_COUNT; r++) {
            map[r] = 0;
            for (int i = 0; i < n_in && i < 64; i++) {
                if (!used[i] && in_sizes[i] == DICT_SIZES[r]) { map[r] = i; used[i] = true; break; }
            }
        }
    }

    const int*   query   = (const int*)d_in[map[R_query]];
    const int*   support = (const int*)d_in[map[R_support]];
    const int*   qlc     = (const int*)d_in[map[R_qlc]];
    const int*   qrc     = (const int*)d_in[map[R_qrc]];
    const int*   slc     = (const int*)d_in[map[R_slc]];
    const int*   srrc    = (const int*)d_in[map[R_src]];
    const float* emb     = (const float*)d_in[map[R_emb]];
    const float* gcnw    = (const float*)d_in[map[R_gcnw]];
    const float* gcnwb   = (const float*)d_in[map[R_gcnwb]];
    const float* gcnb    = (const float*)d_in[map[R_gcnb]];
    const float* p1w     = (const float*)d_in[map[R_p1w]];
    const float* p1b     = (const float*)d_in[map[R_p1b]];
    const float* p2w     = (const float*)d_in[map[R_p2w]];
    const float* p2b     = (const float*)d_in[map[R_p2b]];
    const float* lng     = (const float*)d_in[map[R_lng]];
    const float* lnb     = (const float*)d_in[map[R_lnb]];
    const float* wih     = (const float*)d_in[map[R_wih]];
    const float* whh     = (const float*)d_in[map[R_whh]];
    const float* bih     = (const float*)d_in[map[R_bih]];
    const float* bhh     = (const float*)d_in[map[R_bhh]];
    float* out = (float*)d_out;

    float *mc, *nb, *H, *O, *enc, *sg, *sgn, *sgr, *biasp, *Gbase, *gates, *c, *h;
    cudaGetSymbolAddress((void**)&mc,    g_meancat);
    cudaGetSymbolAddress((void**)&nb,    g_nb);
    cudaGetSymbolAddress((void**)&H,     g_H);
    cudaGetSymbolAddress((void**)&O,     g_O);
    cudaGetSymbolAddress((void**)&enc,   g_enc);
    cudaGetSymbolAddress((void**)&sg,    g_sg);
    cudaGetSymbolAddress((void**)&sgn,   g_sgn);
    cudaGetSymbolAddress((void**)&sgr,   g_sgr);
    cudaGetSymbolAddress((void**)&biasp, g_biasp);
    cudaGetSymbolAddress((void**)&Gbase, g_Gbase);
    cudaGetSymbolAddress((void**)&gates, g_gates);
    cudaGetSymbolAddress((void**)&c,     g_c);
    cudaGetSymbolAddress((void**)&h,     g_h);

    unsigned *wihh, *wihl, *whhh, *whhl, *p1h, *p1l, *p2h, *p2l, *gch, *gcl;
    cudaGetSymbolAddress((void**)&wihh, g_wih_h);  cudaGetSymbolAddress((void**)&wihl, g_wih_l);
    cudaGetSymbolAddress((void**)&whhh, g_whh_h);  cudaGetSymbolAddress((void**)&whhl, g_whh_l);
    cudaGetSymbolAddress((void**)&p1h,  g_p1w_h);  cudaGetSymbolAddress((void**)&p1l,  g_p1w_l);
    cudaGetSymbolAddress((void**)&p2h,  g_p2w_h);  cudaGetSymbolAddress((void**)&p2l,  g_p2w_l);
    cudaGetSymbolAddress((void**)&gch,  g_gcnw_h); cudaGetSymbolAddress((void**)&gcl,  g_gcnw_l);

    float* qg   = enc;
    float* senc = enc + (size_t)BQ * DMV;

    // 0) pack all weights in ONE launch (bf16x2 hi/lo, k16 fragment order)
    PackTable tab;
    tab.seg[0] = { gcnw, gch,  gcl,  512,  0,   32, 0 };
    tab.seg[1] = { p1w,  p1h,  p1l,  512,  0,   32, 64 };
    tab.seg[2] = { p2w,  p2h,  p2l,  1024, 0,   64, 64 + 256 };
    tab.seg[3] = { wih,  wihh, wihl, 512,  HID, 32, 64 + 256 + 256 };
    tab.seg[4] = { whh,  whhh, whhl, 1024, HID, 32, 64 + 256 + 256 + 512 };
    tab.total = 64 + 256 + 256 + 512 + 512;   // 1600
    packw16_all_kernel<<<tab.total, 256>>>(tab);

    // 1) neighbor top-K means -> meancat (4106 x 512)
    nbenc_kernel<<<dim3(BQ + FF, 2), 256>>>(query, support, qlc, qrc, slc, srrc, emb, mc);
    // 2) GCN: nb = tanh(mc @ gcnw^T + wb + b)
    tgemm_bf<1,2><<<dim3(2, 65), 256>>>(mc, 2*DD, MROWS, gch, gcl, 32,
                                        nb, DD, nullptr, 0, gcnwb, gcnb);
    // 3) encoder batched over 2053 rows
    tgemm_bf<2,2><<<dim3(8, 33), 256>>>(nb, DMV, ER, p1h, p1l, 32,
                                        H, 2*DMV, nullptr, 0, p1b, nullptr);
    tgemm_bf<0,2><<<dim3(4, 33), 256>>>(H, 2*DMV, ER, p2h, p2l, 64,
                                        O, DMV, nb, DMV, p2b, nullptr);
    ln_kernel<<<ER, 256>>>(O, enc, lng, lnb);
    // 4) support_g mean + normalized copy
    avgnorm_kernel<<<1, 512>>>(sg, sgn, senc);
    // 5) packed sgr + bias
    pack_kernel<<<NG / 8, 256>>>(sgr, biasp, whh, sg, bih, bhh);

    dim3 gg(16, 16);
    // 6) Gbase = qg @ Wih_sel^T + (bih+bhh)_packed
    tgemm_bf<0,4><<<gg, 256>>>(qg, DMV, BQ, wihh, wihl, 32,
                               Gbase, NG, nullptr, 0, biasp, nullptr);
    // 7) step 1 (c = 0)
    lstm_step_kernel<<<(BQ * DMV) / 256, 256>>>(Gbase, qg, c, h, 1);
    // 8) steps 2..4: gates = h @ Whh_sel[:, :512]^T + Gbase + sgr
    for (int s = 0; s < 3; s++) {
        tgemm_bf<0,4><<<gg, 256>>>(h, DMV, BQ, whhh, whhl, 32,
                                   gates, NG, Gbase, NG, sgr, nullptr);
        lstm_step_kernel<<<(BQ * DMV) / 256, 256>>>(gates, qg, c, h, 0);
    }
    // 9) output cosine
    final_kernel<<<BQ / 8, 256>>>(out, h, sgn);
}